// round 11
// baseline (speedup 1.0000x reference)
#include <cuda_runtime.h>
#include <cuda_bf16.h>
#include <math.h>
#include <stdint.h>

#define BB   2
#define CC   256
#define LL   4096
#define DSZ  16
#define NCH  64
#define CLN  64          // LL / NCH
#define NPOS (BB*LL)     // 8192
#define NBLK 256         // barrier grid size (scanF and out-proj both use 256 blocks)

// weight-split buffer layout (bf16 elements)
#define WOFF_IN(i)   ((i) * 131072)
#define WOFF_XP(i)   (524288 + (i) * 16384)
#define WOFF_OUT(i)  (589824 + (i) * 65536)
#define WTOT 851968

// ---------------- scratch ----------------
__device__ float g_t[NPOS*CC];
__device__ float g_xz[NPOS*2*CC];
__device__ float g_dbl[NPOS*48];
__device__ float g_y[NPOS*CC];
__device__ float g_rowm[NPOS];
__device__ float g_rowrs[NPOS];
__device__ float g_A[4*CC*DSZ];
__device__ int   g_fastA[4];
__device__ float g_cw[4*27*CC];
__device__ float g_P[BB*CC*NCH*DSZ];
__device__ float g_hend[BB*CC*NCH*DSZ];
__device__ float g_hst[BB*CC*NCH*DSZ];
__device__ unsigned g_bar[4];            // monotonic grid-barrier tickets
__device__ __nv_bfloat16 g_ahi[NPOS*CC];
__device__ __nv_bfloat16 g_alo[NPOS*CC];
__device__ __nv_bfloat16 g_whi[WTOT];
__device__ __nv_bfloat16 g_wlo[WTOT];

// ---------------- helpers ----------------
__device__ __forceinline__ uint32_t smem_u32(const void* p) {
    uint32_t a;
    asm("{ .reg .u64 t; cvta.to.shared.u64 t, %1; cvt.u32.u64 %0, t; }" : "=r"(a) : "l"(p));
    return a;
}
__device__ __forceinline__ void warpRed2(float& s, float& s2) {
    #pragma unroll
    for (int o = 16; o; o >>= 1) {
        s  += __shfl_xor_sync(0xffffffffu, s,  o);
        s2 += __shfl_xor_sync(0xffffffffu, s2, o);
    }
}
__device__ __forceinline__ uint32_t packbf2(float a, float b) {
    __nv_bfloat162 t = __floats2bfloat162_rn(a, b);
    return *(uint32_t*)&t;
}
__device__ __forceinline__ void split8_store(const float o[8],
                                             __nv_bfloat16* hiB, __nv_bfloat16* loB,
                                             size_t rowoff, int lane) {
    float hf[8], lf[8];
    #pragma unroll
    for (int k = 0; k < 8; k++) {
        __nv_bfloat16 h = __float2bfloat16(o[k]);
        hf[k] = __bfloat162float(h);
        lf[k] = o[k] - hf[k];
    }
    uint4 uh, ul;
    uh.x = packbf2(hf[0], hf[1]); uh.y = packbf2(hf[2], hf[3]);
    uh.z = packbf2(hf[4], hf[5]); uh.w = packbf2(hf[6], hf[7]);
    ul.x = packbf2(lf[0], lf[1]); ul.y = packbf2(lf[2], lf[3]);
    ul.z = packbf2(lf[4], lf[5]); ul.w = packbf2(lf[6], lf[7]);
    ((uint4*)(hiB + rowoff))[lane] = uh;
    ((uint4*)(loB + rowoff))[lane] = ul;
}
__device__ __forceinline__ void split_store(float v, __nv_bfloat16* hi, __nv_bfloat16* lo, size_t i) {
    __nv_bfloat16 h = __float2bfloat16(v);
    hi[i] = h;
    lo[i] = __float2bfloat16(v - __bfloat162float(h));
}
__device__ __forceinline__ void mma16816(float c[4], const uint32_t a[4],
                                         uint32_t b0, uint32_t b1) {
    asm volatile(
        "mma.sync.aligned.m16n8k16.row.col.f32.bf16.bf16.f32 "
        "{%0,%1,%2,%3}, {%4,%5,%6,%7}, {%8,%9}, {%0,%1,%2,%3};"
        : "+f"(c[0]), "+f"(c[1]), "+f"(c[2]), "+f"(c[3])
        : "r"(a[0]), "r"(a[1]), "r"(a[2]), "r"(a[3]), "r"(b0), "r"(b1));
}
__device__ __forceinline__ void ldsm4(uint32_t r[4], uint32_t addr) {
    asm volatile("ldmatrix.sync.aligned.m8n8.x4.shared.b16 {%0,%1,%2,%3}, [%4];"
        : "=r"(r[0]), "=r"(r[1]), "=r"(r[2]), "=r"(r[3]) : "r"(addr));
}
__device__ __forceinline__ void cpa16(uint32_t saddr, const void* g) {
    asm volatile("cp.async.cg.shared.global [%0], [%1], 16;" :: "r"(saddr), "l"(g));
}
#define CPA_COMMIT() asm volatile("cp.async.commit_group;" ::: "memory")
#define CPA_WAIT(N)  asm volatile("cp.async.wait_group %0;" :: "n"(N) : "memory")

// r^1..r^16 via log-depth tree
__device__ __forceinline__ void rpow16(float rv, float rp[16]) {
    float r2 = rv * rv, r4 = r2 * r2, r8 = r4 * r4;
    rp[0] = rv;        rp[1] = r2;        rp[2] = r2 * rv;   rp[3] = r4;
    rp[4] = r4 * rv;   rp[5] = r4 * r2;   rp[6] = r4 * rp[2]; rp[7] = r8;
    rp[8] = r8 * rv;   rp[9] = r8 * r2;   rp[10] = r8 * rp[2]; rp[11] = r8 * r4;
    rp[12] = r8 * rp[4]; rp[13] = r8 * rp[5]; rp[14] = r8 * rp[6]; rp[15] = r8 * r8;
}

// monotonic-ticket grid barrier (NBLK co-resident blocks; reusable; graph-replay safe)
__device__ __forceinline__ void gridbar(int slot) {
    __syncthreads();
    if (threadIdx.x == 0) {
        __threadfence();
        unsigned ticket = atomicAdd(&g_bar[slot], 1u) + 1u;
        unsigned target = ((ticket - 1u) / NBLK + 1u) * NBLK;
        while ((int)(*(volatile unsigned*)&g_bar[slot] - target) < 0) { }
        __threadfence();
    }
    __syncthreads();
}

// LN + split for one row p (warp-collective), gamma/beta from g/bvec
__device__ __forceinline__ void ln_row(int p, int lane,
                                       const float* __restrict__ g,
                                       const float* __restrict__ bvec) {
    const float4* row = (const float4*)(g_t + (size_t)p * CC);
    float4 v0 = row[lane * 2], v1 = row[lane * 2 + 1];
    float s  = v0.x + v0.y + v0.z + v0.w + v1.x + v1.y + v1.z + v1.w;
    float s2 = v0.x*v0.x + v0.y*v0.y + v0.z*v0.z + v0.w*v0.w
             + v1.x*v1.x + v1.y*v1.y + v1.z*v1.z + v1.w*v1.w;
    warpRed2(s, s2);
    float m  = s * (1.f / CC);
    float rs = rsqrtf(s2 * (1.f / CC) - m * m + 1e-5f);
    float4 gg0 = ((const float4*)g)[lane * 2],    gg1 = ((const float4*)g)[lane * 2 + 1];
    float4 bb0 = ((const float4*)bvec)[lane * 2], bb1 = ((const float4*)bvec)[lane * 2 + 1];
    float o[8];
    o[0] = (v0.x - m) * rs * gg0.x + bb0.x;  o[1] = (v0.y - m) * rs * gg0.y + bb0.y;
    o[2] = (v0.z - m) * rs * gg0.z + bb0.z;  o[3] = (v0.w - m) * rs * gg0.w + bb0.w;
    o[4] = (v1.x - m) * rs * gg1.x + bb1.x;  o[5] = (v1.y - m) * rs * gg1.y + bb1.y;
    o[6] = (v1.z - m) * rs * gg1.z + bb1.z;  o[7] = (v1.w - m) * rs * gg1.w + bb1.w;
    split8_store(o, g_ahi, g_alo, (size_t)p * CC, lane);
}

// ---------------- all-layer weight split ----------------
__global__ void k_wsplit_all(const float* __restrict__ inw,
                             const float* __restrict__ xpw,
                             const float* __restrict__ ow) {
    int idx = blockIdx.x * 256 + threadIdx.x;
    if (idx >= WTOT) return;
    float v;
    if (idx < 524288) {
        v = inw[idx];
    } else if (idx < 589824) {
        int rel = idx - 524288;
        int layer = rel >> 14, w = rel & 16383;
        int row = w >> 8, col = w & 255;
        v = (row < 48) ? xpw[layer * 12288 + row * 256 + col] : 0.f;
    } else {
        v = ow[idx - 589824];
    }
    split_store(v, g_whi, g_wlo, idx);
}

// ---------------- conv weight transpose ----------------
__global__ void k_cwprep(const float* __restrict__ cw) {
    int idx = blockIdx.x * 256 + threadIdx.x;
    if (idx >= 4 * 27 * 256) return;
    int layer = idx / 6912, rem = idx % 6912;
    int j = rem >> 8, c = rem & 255;
    g_cw[idx] = cw[layer * 6912 + c * 27 + j];
}

// ---------------- all-layer A prep ----------------
__global__ void k_prepA_all(const float* __restrict__ alog) {
    int layer = blockIdx.x, c = threadIdx.x;
    __shared__ int ok;
    if (c == 0) ok = 1;
    __syncthreads();
    bool good = true;
    #pragma unroll
    for (int n = 0; n < DSZ; n++) {
        float a = -expf(alog[(layer * 256 + c) * DSZ + n]);
        g_A[(layer * 256 + c) * DSZ + n] = a;
        if (fabsf(a + (float)(n + 1)) > 1e-3f) good = false;
    }
    if (!good) atomicAnd(&ok, 0);
    __syncthreads();
    if (c == 0) g_fastA[layer] = ok;
}

// ---------------- initial transpose ----------------
__global__ void k_init_tr(const float* __restrict__ x) {
    __shared__ float tile[32][33];
    int b = blockIdx.z >> 4, d = blockIdx.z & 15;
    int hw0 = blockIdx.x * 32, c0 = blockIdx.y * 32;
    int tx = threadIdx.x, ty = threadIdx.y;
    tile[ty][tx] = x[((size_t)(b*CC + c0 + ty) * 16 + d) * 256 + hw0 + tx];
    __syncthreads();
    g_t[((size_t)b*LL + (size_t)(hw0 + ty) * 16 + d) * CC + c0 + tx] = tile[tx][ty];
}

// ---------------- LN1 standalone (layer 0 only) ----------------
__global__ __launch_bounds__(256)
void k_ln1(const float* __restrict__ g, const float* __restrict__ bvec) {
    int warp = threadIdx.x >> 5, lane = threadIdx.x & 31;
    int p = blockIdx.x * 8 + warp;
    ln_row(p, lane, g, bvec);
}

// ---------------- pipelined ldmatrix bf16x3 GEMM + fused epilogues ----------------
// mode 0: C = acc
// mode 1: C += acc (residual)
// mode 2: C += acc, then gridbar + next-layer LN1+split (lng/lnb)
// mode 3: C += acc, then gridbar + post-LN stats (g_rowm/g_rowrs)
template<int NT>
__global__ __launch_bounds__(256, 3)
void k_mgemm(const uint32_t* __restrict__ Ahi, const uint32_t* __restrict__ Alo,
             const uint32_t* __restrict__ Bhi, const uint32_t* __restrict__ Blo,
             float* __restrict__ C, int ldc, int Nact, int mode,
             const float* __restrict__ lng, const float* __restrict__ lnb) {
    constexpr int RB = 80;
    constexpr int AL_OFF = 128 * RB;
    constexpr int BH_OFF = 2 * 128 * RB;
    constexpr int BL_OFF = BH_OFF + NT * RB;
    constexpr int STAGE  = BH_OFF + 2 * NT * RB;
    constexpr int NTILES = NT / 16;
    constexpr int NPAIR  = NTILES / 2;

    extern __shared__ __align__(16) char smem[];
    uint32_t sbase = smem_u32(smem);
    int tid = threadIdx.x, wid = tid >> 5, lane = tid & 31;
    int g2 = lane >> 2, t4 = lane & 3;
    int row0 = blockIdx.y * 128, col0 = blockIdx.x * NT;
    int m0 = (wid >> 1) * 32, n0 = (wid & 1) * (NT / 2);
    uint32_t lmo = (uint32_t)(((lane & 7) + ((lane >> 3) & 1) * 8) * RB + (lane >> 4) * 16);

    float acc[2][NTILES][4];
    #pragma unroll
    for (int mt = 0; mt < 2; mt++)
        #pragma unroll
        for (int nt = 0; nt < NTILES; nt++)
            #pragma unroll
            for (int j = 0; j < 4; j++) acc[mt][nt][j] = 0.f;

    int lr = tid >> 2, lc4 = (tid & 3) * 4;

    auto load_chunk = [&](int kc, int stg) {
        uint32_t sb = sbase + stg * STAGE;
        int kw = kc * 16;
        #pragma unroll
        for (int i = 0; i < 2; i++) {
            int r = lr + i * 64;
            size_t gi = (size_t)(row0 + r) * 128 + kw + lc4;
            uint32_t so = (uint32_t)(r * RB + lc4 * 4);
            cpa16(sb + so,          Ahi + gi);
            cpa16(sb + AL_OFF + so, Alo + gi);
        }
        #pragma unroll
        for (int i = 0; i < NT / 64; i++) {
            int r = lr + i * 64;
            size_t gi = (size_t)(col0 + r) * 128 + kw + lc4;
            uint32_t so = (uint32_t)(r * RB + lc4 * 4);
            cpa16(sb + BH_OFF + so, Bhi + gi);
            cpa16(sb + BL_OFF + so, Blo + gi);
        }
    };

    load_chunk(0, 0); CPA_COMMIT();
    load_chunk(1, 1); CPA_COMMIT();

    #pragma unroll 1
    for (int kc = 0; kc < 8; kc++) {
        if (kc < 7) { CPA_WAIT(1); } else { CPA_WAIT(0); }
        __syncthreads();
        uint32_t sb = sbase + (kc & 1) * STAGE;
        uint32_t aH = sb + m0 * RB + lmo;
        uint32_t aL = aH + AL_OFF;
        uint32_t bH = sb + BH_OFF + n0 * RB + lmo;
        uint32_t bL = bH + NT * RB;
        #pragma unroll
        for (int step = 0; step < 2; step++) {
            uint32_t ko = step * 32;
            uint32_t ah[2][4], al[2][4];
            #pragma unroll
            for (int mt = 0; mt < 2; mt++) {
                ldsm4(ah[mt], aH + mt * 16 * RB + ko);
                ldsm4(al[mt], aL + mt * 16 * RB + ko);
            }
            #pragma unroll
            for (int p = 0; p < NPAIR; p++) {
                uint32_t bh[4], bl[4];
                ldsm4(bh, bH + p * 16 * RB + ko);
                ldsm4(bl, bL + p * 16 * RB + ko);
                #pragma unroll
                for (int sub = 0; sub < 2; sub++) {
                    uint32_t b0h = bh[sub], b1h = bh[2 + sub];
                    uint32_t b0l = bl[sub], b1l = bl[2 + sub];
                    #pragma unroll
                    for (int mt = 0; mt < 2; mt++) {
                        mma16816(acc[mt][2 * p + sub], ah[mt], b0h, b1h);
                        mma16816(acc[mt][2 * p + sub], ah[mt], b0l, b1l);
                        mma16816(acc[mt][2 * p + sub], al[mt], b0h, b1h);
                    }
                }
            }
        }
        __syncthreads();
        if (kc + 2 < 8) { load_chunk(kc + 2, kc & 1); CPA_COMMIT(); }
    }

    #pragma unroll
    for (int mt = 0; mt < 2; mt++) {
        int rA = row0 + m0 + mt * 16 + g2;
        int rB = rA + 8;
        #pragma unroll
        for (int nt = 0; nt < NTILES; nt++) {
            int cA = col0 + n0 + nt * 8 + 2 * t4;
            #pragma unroll
            for (int j = 0; j < 2; j++) {
                int c = cA + j;
                if (c < Nact) {
                    float v0 = acc[mt][nt][j];
                    float v1 = acc[mt][nt][2 + j];
                    if (mode >= 1) {
                        v0 += C[(size_t)rA * ldc + c];
                        v1 += C[(size_t)rB * ldc + c];
                    }
                    C[(size_t)rA * ldc + c] = v0;
                    C[(size_t)rB * ldc + c] = v1;
                }
            }
        }
    }

    // fused post-GEMM phase (out-proj only; grid must be exactly NBLK blocks)
    if (mode >= 2) {
        gridbar(3);
        int bid = blockIdx.y * gridDim.x + blockIdx.x;   // 0..255
        if (mode == 2) {
            #pragma unroll
            for (int rr = 0; rr < 4; rr++) {
                int p = bid * 32 + wid * 4 + rr;
                ln_row(p, lane, lng, lnb);
            }
        } else {
            #pragma unroll
            for (int rr = 0; rr < 4; rr++) {
                int p = bid * 32 + wid * 4 + rr;
                const float4* row = (const float4*)(g_t + (size_t)p * CC);
                float4 v0 = row[lane * 2], v1 = row[lane * 2 + 1];
                float s  = v0.x + v0.y + v0.z + v0.w + v1.x + v1.y + v1.z + v1.w;
                float s2 = v0.x*v0.x + v0.y*v0.y + v0.z*v0.z + v0.w*v0.w
                         + v1.x*v1.x + v1.y*v1.y + v1.z*v1.z + v1.w*v1.w;
                warpRed2(s, s2);
                if (lane == 0) {
                    float m = s * (1.f / CC);
                    g_rowm[p] = m;
                    g_rowrs[p] = rsqrtf(s2 * (1.f / CC) - m * m + 1e-5f);
                }
            }
        }
    }
}

// ---------------- depthwise 3x3x3 conv + SiLU + flip ----------------
__global__ __launch_bounds__(256)
void k_conv(int layer, const float* __restrict__ convb, int ori) {
    int bidx = blockIdx.x;
    int b = bidx >> 8, h = (bidx >> 4) & 15, w = bidx & 15;
    int c = threadIdx.x;
    const float* wt = g_cw + layer * 6912;
    float wr[27];
    #pragma unroll
    for (int j = 0; j < 27; j++) wr[j] = wt[j * 256 + c];
    float bias = convb[c];
    float acc[16];
    #pragma unroll
    for (int d = 0; d < 16; d++) acc[d] = bias;

    #pragma unroll
    for (int s1 = 0; s1 < 3; s1++) {
        int hh = h + s1 - 1; if (hh < 0 || hh > 15) continue;
        #pragma unroll
        for (int s2 = 0; s2 < 3; s2++) {
            int ww = w + s2 - 1; if (ww < 0 || ww > 15) continue;
            size_t cb = ((size_t)(b * LL + (hh * 16 + ww) * 16)) * 512 + c;
            float col[16];
            #pragma unroll
            for (int dd = 0; dd < 16; dd++) col[dd] = g_xz[cb + (size_t)dd * 512];
            float w0 = wr[s1 * 9 + s2 * 3 + 0];
            float w1 = wr[s1 * 9 + s2 * 3 + 1];
            float w2 = wr[s1 * 9 + s2 * 3 + 2];
            #pragma unroll
            for (int d = 0; d < 16; d++) {
                float a = w1 * col[d];
                if (d > 0)  a += w0 * col[d - 1];
                if (d < 15) a += w2 * col[d + 1];
                acc[d] += a;
            }
        }
    }
    int fh = (ori & 1) ? 15 - h : h;
    int fw = (ori & 2) ? 15 - w : w;
    #pragma unroll
    for (int d = 0; d < 16; d++) {
        float sv = acc[d] / (1.f + expf(-acc[d]));
        int fd = (ori & 4) ? 15 - d : d;
        size_t oi = ((size_t)b * LL + (fh * 16 + fw) * 16 + fd) * CC + c;
        split_store(sv, g_ahi, g_alo, oi);
    }
}

// ---------------- FUSED selective scan + gate: phases A+B+C+D ----------------
__global__ __launch_bounds__(128)
void k_scanF(int layer, const float* __restrict__ dtw_, const float* __restrict__ dtb_,
             const float* __restrict__ Dv, int ori,
             const float* __restrict__ og, const float* __restrict__ ob) {
    extern __shared__ float sm[];
    float* rvS  = sm;                    // [CLN*128]
    float* dxS  = sm + CLN * 128;
    float* xvS  = sm + 2 * CLN * 128;
    float* Bsm  = sm + 3 * CLN * 128;    // [CLN*16]
    float* Csm  = Bsm + CLN * 16;
    float* dtsm = Csm + CLN * 16;

    int tid = threadIdx.x;
    int c = blockIdx.y * 128 + tid;
    int ch = blockIdx.x, b = blockIdx.z;
    int fast = g_fastA[layer];

    for (int i = tid; i < CLN * 48; i += 128) {
        int t = i / 48, j = i % 48;
        float v = g_dbl[((size_t)b * LL + ch * CLN + t) * 48 + j];
        if (j < 16) dtsm[t * 16 + j] = v;
        else if (j < 32) Bsm[t * 16 + (j - 16)] = v;
        else Csm[t * 16 + (j - 32)] = v;
    }
    __syncthreads();

    float dw[DSZ];
    #pragma unroll
    for (int j = 0; j < DSZ; j++) dw[j] = dtw_[c * DSZ + j];
    float db = dtb_[c];

    // ---- phase A ----
    float h[DSZ], P[DSZ];
    #pragma unroll
    for (int n = 0; n < DSZ; n++) { h[n] = 0.f; P[n] = 1.f; }
    size_t base = ((size_t)b * LL + ch * CLN) * CC + c;
    if (fast) {
        #pragma unroll 4
        for (int t = 0; t < CLN; t++) {
            size_t gi = base + (size_t)t * CC;
            float xv = __bfloat162float(g_ahi[gi]) + __bfloat162float(g_alo[gi]);
            float traw = db;
            #pragma unroll
            for (int j = 0; j < DSZ; j++) traw += dw[j] * dtsm[t * 16 + j];
            float sp = fmaxf(traw, 0.f) + log1pf(expf(-fabsf(traw)));
            float rv = expf(-sp);
            float dtx = sp * xv;
            rvS[t * 128 + tid] = rv;
            dxS[t * 128 + tid] = dtx;
            xvS[t * 128 + tid] = xv;
            float rp[16];
            rpow16(rv, rp);
            #pragma unroll
            for (int n = 0; n < DSZ; n++) {
                h[n] = rp[n] * h[n] + dtx * Bsm[t * 16 + n];
                P[n] *= rp[n];
            }
        }
    } else {
        #pragma unroll 2
        for (int t = 0; t < CLN; t++) {
            size_t gi = base + (size_t)t * CC;
            float xv = __bfloat162float(g_ahi[gi]) + __bfloat162float(g_alo[gi]);
            float traw = db;
            #pragma unroll
            for (int j = 0; j < DSZ; j++) traw += dw[j] * dtsm[t * 16 + j];
            float sp = fmaxf(traw, 0.f) + log1pf(expf(-fabsf(traw)));
            float dtx = sp * xv;
            rvS[t * 128 + tid] = sp;
            dxS[t * 128 + tid] = dtx;
            xvS[t * 128 + tid] = xv;
            #pragma unroll
            for (int n = 0; n < DSZ; n++) {
                float dA = __expf(sp * g_A[((layer * 256) + c) * DSZ + n]);
                h[n] = dA * h[n] + dtx * Bsm[t * 16 + n];
                P[n] *= dA;
            }
        }
    }
    size_t off = (((size_t)(b * CC + c)) * NCH + ch) * DSZ;
    #pragma unroll
    for (int n = 0; n < DSZ; n++) { g_hend[off + n] = h[n]; g_P[off + n] = P[n]; }

    gridbar(0);

    // ---- phase B ----
    {
        int rank = ((blockIdx.z * 2 + blockIdx.y) * NCH + blockIdx.x) * 128 + tid;
        if (rank < BB * CC * DSZ) {
            int n = rank & 15, bc = rank >> 4;
            float H = 0.f;
            size_t bb2 = (size_t)bc * NCH * DSZ + n;
            for (int k0 = 0; k0 < NCH; k0 += 8) {
                float Pv[8], Ev[8];
                #pragma unroll
                for (int q = 0; q < 8; q++) {
                    size_t o = bb2 + (size_t)(k0 + q) * DSZ;
                    Pv[q] = g_P[o];
                    Ev[q] = g_hend[o];
                }
                #pragma unroll
                for (int q = 0; q < 8; q++) {
                    g_hst[bb2 + (size_t)(k0 + q) * DSZ] = H;
                    H = Pv[q] * H + Ev[q];
                }
            }
        }
    }

    gridbar(1);

    // ---- phase C ----
    #pragma unroll
    for (int n = 0; n < DSZ; n++) h[n] = g_hst[off + n];
    float Dc = Dv[c];
    if (fast) {
        #pragma unroll 4
        for (int t = 0; t < CLN; t++) {
            float rv  = rvS[t * 128 + tid];
            float dtx = dxS[t * 128 + tid];
            float xv  = xvS[t * 128 + tid];
            float rp[16];
            rpow16(rv, rp);
            float y = 0.f;
            #pragma unroll
            for (int n = 0; n < DSZ; n++) {
                h[n] = rp[n] * h[n] + dtx * Bsm[t * 16 + n];
                y += h[n] * Csm[t * 16 + n];
            }
            g_y[base + (size_t)t * CC] = y + Dc * xv;
        }
    } else {
        #pragma unroll 2
        for (int t = 0; t < CLN; t++) {
            float sp  = rvS[t * 128 + tid];
            float dtx = dxS[t * 128 + tid];
            float xv  = xvS[t * 128 + tid];
            float y = 0.f;
            #pragma unroll
            for (int n = 0; n < DSZ; n++) {
                float dA = __expf(sp * g_A[((layer * 256) + c) * DSZ + n]);
                h[n] = dA * h[n] + dtx * Bsm[t * 16 + n];
                y += h[n] * Csm[t * 16 + n];
            }
            g_y[base + (size_t)t * CC] = y + Dc * xv;
        }
    }

    gridbar(2);

    // ---- phase D: unflip + output LN + SiLU gate -> splits ----
    {
        int bid = (blockIdx.z * 2 + blockIdx.y) * NCH + blockIdx.x;   // 0..255
        int warp = tid >> 5, lane = tid & 31;
        #pragma unroll
        for (int rr = 0; rr < 8; rr++) {
            int p = bid * 32 + warp * 8 + rr;
            int b2 = p >> 12, l = p & 4095;
            int hh = l >> 8, ww = (l >> 4) & 15, dd = l & 15;
            if (ori & 1) hh = 15 - hh;
            if (ori & 2) ww = 15 - ww;
            if (ori & 4) dd = 15 - dd;
            int ls = (hh << 8) | (ww << 4) | dd;
            const float4* yr = (const float4*)(g_y + ((size_t)((b2 << 12) | ls)) * CC);
            float4 v0 = yr[lane * 2], v1 = yr[lane * 2 + 1];
            float s  = v0.x + v0.y + v0.z + v0.w + v1.x + v1.y + v1.z + v1.w;
            float s2 = v0.x*v0.x + v0.y*v0.y + v0.z*v0.z + v0.w*v0.w
                     + v1.x*v1.x + v1.y*v1.y + v1.z*v1.z + v1.w*v1.w;
            warpRed2(s, s2);
            float m  = s * (1.f / CC);
            float rs = rsqrtf(s2 * (1.f / CC) - m * m + 1e-5f);
            const float4* zr = (const float4*)(g_xz + (size_t)p * 512 + 256);
            float4 z0 = zr[lane * 2], z1 = zr[lane * 2 + 1];
            float4 gg0 = ((const float4*)og)[lane * 2], gg1 = ((const float4*)og)[lane * 2 + 1];
            float4 bb0 = ((const float4*)ob)[lane * 2], bb1 = ((const float4*)ob)[lane * 2 + 1];
            float vv[8] = {v0.x, v0.y, v0.z, v0.w, v1.x, v1.y, v1.z, v1.w};
            float zz[8] = {z0.x, z0.y, z0.z, z0.w, z1.x, z1.y, z1.z, z1.w};
            float ga[8] = {gg0.x, gg0.y, gg0.z, gg0.w, gg1.x, gg1.y, gg1.z, gg1.w};
            float ba[8] = {bb0.x, bb0.y, bb0.z, bb0.w, bb1.x, bb1.y, bb1.z, bb1.w};
            float o[8];
            #pragma unroll
            for (int k = 0; k < 8; k++) {
                float sz = zz[k] / (1.f + expf(-zz[k]));
                o[k] = ((vv[k] - m) * rs * ga[k] + ba[k]) * sz;
            }
            split8_store(o, g_ahi, g_alo, (size_t)p * CC, lane);
        }
    }
}

// ---------------- final transpose + post-LN apply ----------------
__global__ void k_final_tr(float* __restrict__ out,
                           const float* __restrict__ pg, const float* __restrict__ pb) {
    __shared__ float tile[32][33];
    int b = blockIdx.z >> 4, d = blockIdx.z & 15;
    int hw0 = blockIdx.x * 32, c0 = blockIdx.y * 32;
    int tx = threadIdx.x, ty = threadIdx.y;
    int p = b * LL + (hw0 + ty) * 16 + d;
    int c = c0 + tx;
    float v = g_t[(size_t)p * CC + c];
    tile[ty][tx] = (v - g_rowm[p]) * g_rowrs[p] * pg[c] + pb[c];
    __syncthreads();
    out[((size_t)(b * CC + c0 + ty) * 16 + d) * 256 + hw0 + tx] = tile[tx][ty];
}

// ---------------- host ----------------
extern "C" void kernel_launch(void* const* d_in, const int* in_sizes, int n_in,
                              void* d_out, int out_size) {
    const float* x       = (const float*)d_in[0];
    const float* in_w    = (const float*)d_in[1];
    const float* conv_w  = (const float*)d_in[2];
    const float* conv_b  = (const float*)d_in[3];
    const float* xproj_w = (const float*)d_in[4];
    const float* dt_w    = (const float*)d_in[5];
    const float* dt_b    = (const float*)d_in[6];
    const float* A_log   = (const float*)d_in[7];
    const float* D_skip  = (const float*)d_in[8];
    const float* on_g    = (const float*)d_in[9];
    const float* on_b    = (const float*)d_in[10];
    const float* out_w   = (const float*)d_in[11];
    const float* ln1_g   = (const float*)d_in[12];
    const float* ln1_b   = (const float*)d_in[13];
    const float* post_g  = (const float*)d_in[14];
    const float* post_b  = (const float*)d_in[15];
    float* out = (float*)d_out;

    void *p_t, *p_xz, *p_dbl, *p_ahi, *p_alo, *p_whi, *p_wlo;
    cudaGetSymbolAddress(&p_t,   g_t);
    cudaGetSymbolAddress(&p_xz,  g_xz);
    cudaGetSymbolAddress(&p_dbl, g_dbl);
    cudaGetSymbolAddress(&p_ahi, g_ahi);
    cudaGetSymbolAddress(&p_alo, g_alo);
    cudaGetSymbolAddress(&p_whi, g_whi);
    cudaGetSymbolAddress(&p_wlo, g_wlo);
    const uint32_t* whi = (const uint32_t*)p_whi;
    const uint32_t* wlo = (const uint32_t*)p_wlo;

    const int SM64  = 2 * (2 * 128 * 80 + 2 * 64 * 80);        // 61440 B
    const int SMEMF = (3 * CLN * 128 + 3 * CLN * 16) * 4;      // 110592 B
    static int attr_done = 0;
    if (!attr_done) {
        cudaFuncSetAttribute(k_mgemm<64>, cudaFuncAttributeMaxDynamicSharedMemorySize, SM64);
        cudaFuncSetAttribute(k_scanF,     cudaFuncAttributeMaxDynamicSharedMemorySize, SMEMF);
        attr_done = 1;
    }

    k_wsplit_all<<<(WTOT + 255) / 256, 256>>>(in_w, xproj_w, out_w);
    k_cwprep<<<108, 256>>>(conv_w);
    k_prepA_all<<<4, 256>>>(A_log);
    k_init_tr<<<dim3(8, 8, 32), dim3(32, 32)>>>(x);
    k_ln1<<<1024, 256>>>(ln1_g, ln1_b);          // layer 0 LN only

    for (int i = 0; i < 4; i++) {
        int ori = i;  // i % 8
        // in-proj: (8192 x 512)
        k_mgemm<64><<<dim3(8, 64), 256, SM64>>>(
            (const uint32_t*)p_ahi, (const uint32_t*)p_alo,
            whi + WOFF_IN(i) / 2, wlo + WOFF_IN(i) / 2,
            (float*)p_xz, 512, 512, 0, nullptr, nullptr);
        k_conv<<<BB * 256, 256>>>(i, conv_b + i * 256, ori);
        // xproj: (8192 x 48)
        k_mgemm<64><<<dim3(1, 64), 256, SM64>>>(
            (const uint32_t*)p_ahi, (const uint32_t*)p_alo,
            whi + WOFF_XP(i) / 2, wlo + WOFF_XP(i) / 2,
            (float*)p_dbl, 48, 48, 0, nullptr, nullptr);
        // fused scan (A+B+C) + gate (D)
        k_scanF<<<dim3(NCH, 2, BB), 128, SMEMF>>>(i, dt_w + (size_t)i * 4096,
                                                  dt_b + i * 256, D_skip + i * 256,
                                                  ori, on_g + i * 256, on_b + i * 256);
        // out-proj + residual + (next-layer LN1 | post-stats)
        int mode = (i < 3) ? 2 : 3;
        k_mgemm<64><<<dim3(4, 64), 256, SM64>>>(
            (const uint32_t*)p_ahi, (const uint32_t*)p_alo,
            whi + WOFF_OUT(i) / 2, wlo + WOFF_OUT(i) / 2,
            (float*)p_t, 256, 256, mode,
            ln1_g + (i + 1) * 256 * (i < 3), ln1_b + (i + 1) * 256 * (i < 3));
    }

    k_final_tr<<<dim3(8, 8, 32), dim3(32, 32)>>>(out, post_g, post_b);
}

// round 12
// speedup vs baseline: 1.0007x; 1.0007x over previous
#include <cuda_runtime.h>
#include <cuda_bf16.h>
#include <math.h>
#include <stdint.h>

#define BB   2
#define CC   256
#define LL   4096
#define DSZ  16
#define NCH  64
#define CLN  64          // LL / NCH
#define NPOS (BB*LL)     // 8192
#define NBLK 256         // fused-scan grid size (co-resident by construction)

// weight-split buffer layout (bf16 elements)
#define WOFF_IN(i)   ((i) * 131072)
#define WOFF_XP(i)   (524288 + (i) * 16384)
#define WOFF_OUT(i)  (589824 + (i) * 65536)
#define WTOT 851968

// ---------------- scratch ----------------
__device__ float g_t[NPOS*CC];
__device__ float g_xz[NPOS*2*CC];
__device__ float g_dbl[NPOS*48];
__device__ float g_y[NPOS*CC];
__device__ float g_rowm[NPOS];
__device__ float g_rowrs[NPOS];
__device__ float g_A[4*CC*DSZ];
__device__ int   g_fastA[4];
__device__ float g_cw[4*27*CC];
__device__ float g_P[BB*CC*NCH*DSZ];
__device__ float g_hend[BB*CC*NCH*DSZ];
__device__ float g_hst[BB*CC*NCH*DSZ];
__device__ unsigned g_bar[3];            // monotonic grid-barrier tickets
__device__ __nv_bfloat16 g_ahi[NPOS*CC];
__device__ __nv_bfloat16 g_alo[NPOS*CC];
__device__ __nv_bfloat16 g_whi[WTOT];
__device__ __nv_bfloat16 g_wlo[WTOT];

// ---------------- helpers ----------------
__device__ __forceinline__ uint32_t smem_u32(const void* p) {
    uint32_t a;
    asm("{ .reg .u64 t; cvta.to.shared.u64 t, %1; cvt.u32.u64 %0, t; }" : "=r"(a) : "l"(p));
    return a;
}
__device__ __forceinline__ void warpRed2(float& s, float& s2) {
    #pragma unroll
    for (int o = 16; o; o >>= 1) {
        s  += __shfl_xor_sync(0xffffffffu, s,  o);
        s2 += __shfl_xor_sync(0xffffffffu, s2, o);
    }
}
__device__ __forceinline__ uint32_t packbf2(float a, float b) {
    __nv_bfloat162 t = __floats2bfloat162_rn(a, b);
    return *(uint32_t*)&t;
}
__device__ __forceinline__ void split8_store(const float o[8],
                                             __nv_bfloat16* hiB, __nv_bfloat16* loB,
                                             size_t rowoff, int lane) {
    float hf[8], lf[8];
    #pragma unroll
    for (int k = 0; k < 8; k++) {
        __nv_bfloat16 h = __float2bfloat16(o[k]);
        hf[k] = __bfloat162float(h);
        lf[k] = o[k] - hf[k];
    }
    uint4 uh, ul;
    uh.x = packbf2(hf[0], hf[1]); uh.y = packbf2(hf[2], hf[3]);
    uh.z = packbf2(hf[4], hf[5]); uh.w = packbf2(hf[6], hf[7]);
    ul.x = packbf2(lf[0], lf[1]); ul.y = packbf2(lf[2], lf[3]);
    ul.z = packbf2(lf[4], lf[5]); ul.w = packbf2(lf[6], lf[7]);
    ((uint4*)(hiB + rowoff))[lane] = uh;
    ((uint4*)(loB + rowoff))[lane] = ul;
}
__device__ __forceinline__ void split_store(float v, __nv_bfloat16* hi, __nv_bfloat16* lo, size_t i) {
    __nv_bfloat16 h = __float2bfloat16(v);
    hi[i] = h;
    lo[i] = __float2bfloat16(v - __bfloat162float(h));
}
__device__ __forceinline__ void mma16816(float c[4], const uint32_t a[4],
                                         uint32_t b0, uint32_t b1) {
    asm volatile(
        "mma.sync.aligned.m16n8k16.row.col.f32.bf16.bf16.f32 "
        "{%0,%1,%2,%3}, {%4,%5,%6,%7}, {%8,%9}, {%0,%1,%2,%3};"
        : "+f"(c[0]), "+f"(c[1]), "+f"(c[2]), "+f"(c[3])
        : "r"(a[0]), "r"(a[1]), "r"(a[2]), "r"(a[3]), "r"(b0), "r"(b1));
}
__device__ __forceinline__ void ldsm4(uint32_t r[4], uint32_t addr) {
    asm volatile("ldmatrix.sync.aligned.m8n8.x4.shared.b16 {%0,%1,%2,%3}, [%4];"
        : "=r"(r[0]), "=r"(r[1]), "=r"(r[2]), "=r"(r[3]) : "r"(addr));
}
__device__ __forceinline__ void cpa16(uint32_t saddr, const void* g) {
    asm volatile("cp.async.cg.shared.global [%0], [%1], 16;" :: "r"(saddr), "l"(g));
}
#define CPA_COMMIT() asm volatile("cp.async.commit_group;" ::: "memory")
#define CPA_WAIT(N)  asm volatile("cp.async.wait_group %0;" :: "n"(N) : "memory")

// r^1..r^16 via log-depth tree
__device__ __forceinline__ void rpow16(float rv, float rp[16]) {
    float r2 = rv * rv, r4 = r2 * r2, r8 = r4 * r4;
    rp[0] = rv;        rp[1] = r2;        rp[2] = r2 * rv;   rp[3] = r4;
    rp[4] = r4 * rv;   rp[5] = r4 * r2;   rp[6] = r4 * rp[2]; rp[7] = r8;
    rp[8] = r8 * rv;   rp[9] = r8 * r2;   rp[10] = r8 * rp[2]; rp[11] = r8 * r4;
    rp[12] = r8 * rp[4]; rp[13] = r8 * rp[5]; rp[14] = r8 * rp[6]; rp[15] = r8 * r8;
}

// monotonic-ticket grid barrier (all NBLK blocks co-resident; graph-replay safe)
__device__ __forceinline__ void gridbar(int slot) {
    __syncthreads();
    if (threadIdx.x == 0) {
        __threadfence();
        unsigned ticket = atomicAdd(&g_bar[slot], 1u) + 1u;
        unsigned target = ((ticket - 1u) / NBLK + 1u) * NBLK;
        while ((int)(*(volatile unsigned*)&g_bar[slot] - target) < 0) { }
        __threadfence();
    }
    __syncthreads();
}

// ---------------- all-layer weight split ----------------
__global__ void k_wsplit_all(const float* __restrict__ inw,
                             const float* __restrict__ xpw,
                             const float* __restrict__ ow) {
    int idx = blockIdx.x * 256 + threadIdx.x;
    if (idx >= WTOT) return;
    float v;
    if (idx < 524288) {
        v = inw[idx];
    } else if (idx < 589824) {
        int rel = idx - 524288;
        int layer = rel >> 14, w = rel & 16383;
        int row = w >> 8, col = w & 255;
        v = (row < 48) ? xpw[layer * 12288 + row * 256 + col] : 0.f;
    } else {
        v = ow[idx - 589824];
    }
    split_store(v, g_whi, g_wlo, idx);
}

// ---------------- conv weight transpose ----------------
__global__ void k_cwprep(const float* __restrict__ cw) {
    int idx = blockIdx.x * 256 + threadIdx.x;
    if (idx >= 4 * 27 * 256) return;
    int layer = idx / 6912, rem = idx % 6912;
    int j = rem >> 8, c = rem & 255;
    g_cw[idx] = cw[layer * 6912 + c * 27 + j];
}

// ---------------- all-layer A prep ----------------
__global__ void k_prepA_all(const float* __restrict__ alog) {
    int layer = blockIdx.x, c = threadIdx.x;
    __shared__ int ok;
    if (c == 0) ok = 1;
    __syncthreads();
    bool good = true;
    #pragma unroll
    for (int n = 0; n < DSZ; n++) {
        float a = -expf(alog[(layer * 256 + c) * DSZ + n]);
        g_A[(layer * 256 + c) * DSZ + n] = a;
        if (fabsf(a + (float)(n + 1)) > 1e-3f) good = false;
    }
    if (!good) atomicAnd(&ok, 0);
    __syncthreads();
    if (c == 0) g_fastA[layer] = ok;
}

// ---------------- initial transpose ----------------
__global__ void k_init_tr(const float* __restrict__ x) {
    __shared__ float tile[32][33];
    int b = blockIdx.z >> 4, d = blockIdx.z & 15;
    int hw0 = blockIdx.x * 32, c0 = blockIdx.y * 32;
    int tx = threadIdx.x, ty = threadIdx.y;
    tile[ty][tx] = x[((size_t)(b*CC + c0 + ty) * 16 + d) * 256 + hw0 + tx];
    __syncthreads();
    g_t[((size_t)b*LL + (size_t)(hw0 + ty) * 16 + d) * CC + c0 + tx] = tile[tx][ty];
}

// ---------------- LN1 (warp per row) + bf16 split ----------------
__global__ __launch_bounds__(256)
void k_ln1(const float* __restrict__ g, const float* __restrict__ bvec) {
    int warp = threadIdx.x >> 5, lane = threadIdx.x & 31;
    int p = blockIdx.x * 8 + warp;
    const float4* row = (const float4*)(g_t + (size_t)p * CC);
    float4 v0 = row[lane * 2], v1 = row[lane * 2 + 1];
    float s  = v0.x + v0.y + v0.z + v0.w + v1.x + v1.y + v1.z + v1.w;
    float s2 = v0.x*v0.x + v0.y*v0.y + v0.z*v0.z + v0.w*v0.w
             + v1.x*v1.x + v1.y*v1.y + v1.z*v1.z + v1.w*v1.w;
    warpRed2(s, s2);
    float m  = s * (1.f / CC);
    float rs = rsqrtf(s2 * (1.f / CC) - m * m + 1e-5f);
    float4 gg0 = ((const float4*)g)[lane * 2],    gg1 = ((const float4*)g)[lane * 2 + 1];
    float4 bb0 = ((const float4*)bvec)[lane * 2], bb1 = ((const float4*)bvec)[lane * 2 + 1];
    float o[8];
    o[0] = (v0.x - m) * rs * gg0.x + bb0.x;  o[1] = (v0.y - m) * rs * gg0.y + bb0.y;
    o[2] = (v0.z - m) * rs * gg0.z + bb0.z;  o[3] = (v0.w - m) * rs * gg0.w + bb0.w;
    o[4] = (v1.x - m) * rs * gg1.x + bb1.x;  o[5] = (v1.y - m) * rs * gg1.y + bb1.y;
    o[6] = (v1.z - m) * rs * gg1.z + bb1.z;  o[7] = (v1.w - m) * rs * gg1.w + bb1.w;
    split8_store(o, g_ahi, g_alo, (size_t)p * CC, lane);
}

// ---------------- pipelined ldmatrix bf16x3 GEMM (pristine R10 form) ----------------
template<int NT>
__global__ __launch_bounds__(256, 3)
void k_mgemm(const uint32_t* __restrict__ Ahi, const uint32_t* __restrict__ Alo,
             const uint32_t* __restrict__ Bhi, const uint32_t* __restrict__ Blo,
             float* __restrict__ C, int ldc, int Nact, int mode) {
    constexpr int RB = 80;
    constexpr int AL_OFF = 128 * RB;
    constexpr int BH_OFF = 2 * 128 * RB;
    constexpr int BL_OFF = BH_OFF + NT * RB;
    constexpr int STAGE  = BH_OFF + 2 * NT * RB;
    constexpr int NTILES = NT / 16;
    constexpr int NPAIR  = NTILES / 2;

    extern __shared__ __align__(16) char smem[];
    uint32_t sbase = smem_u32(smem);
    int tid = threadIdx.x, wid = tid >> 5, lane = tid & 31;
    int g2 = lane >> 2, t4 = lane & 3;
    int row0 = blockIdx.y * 128, col0 = blockIdx.x * NT;
    int m0 = (wid >> 1) * 32, n0 = (wid & 1) * (NT / 2);
    uint32_t lmo = (uint32_t)(((lane & 7) + ((lane >> 3) & 1) * 8) * RB + (lane >> 4) * 16);

    float acc[2][NTILES][4];
    #pragma unroll
    for (int mt = 0; mt < 2; mt++)
        #pragma unroll
        for (int nt = 0; nt < NTILES; nt++)
            #pragma unroll
            for (int j = 0; j < 4; j++) acc[mt][nt][j] = 0.f;

    int lr = tid >> 2, lc4 = (tid & 3) * 4;

    auto load_chunk = [&](int kc, int stg) {
        uint32_t sb = sbase + stg * STAGE;
        int kw = kc * 16;
        #pragma unroll
        for (int i = 0; i < 2; i++) {
            int r = lr + i * 64;
            size_t gi = (size_t)(row0 + r) * 128 + kw + lc4;
            uint32_t so = (uint32_t)(r * RB + lc4 * 4);
            cpa16(sb + so,          Ahi + gi);
            cpa16(sb + AL_OFF + so, Alo + gi);
        }
        #pragma unroll
        for (int i = 0; i < NT / 64; i++) {
            int r = lr + i * 64;
            size_t gi = (size_t)(col0 + r) * 128 + kw + lc4;
            uint32_t so = (uint32_t)(r * RB + lc4 * 4);
            cpa16(sb + BH_OFF + so, Bhi + gi);
            cpa16(sb + BL_OFF + so, Blo + gi);
        }
    };

    load_chunk(0, 0); CPA_COMMIT();
    load_chunk(1, 1); CPA_COMMIT();

    #pragma unroll 1
    for (int kc = 0; kc < 8; kc++) {
        if (kc < 7) { CPA_WAIT(1); } else { CPA_WAIT(0); }
        __syncthreads();
        uint32_t sb = sbase + (kc & 1) * STAGE;
        uint32_t aH = sb + m0 * RB + lmo;
        uint32_t aL = aH + AL_OFF;
        uint32_t bH = sb + BH_OFF + n0 * RB + lmo;
        uint32_t bL = bH + NT * RB;
        #pragma unroll
        for (int step = 0; step < 2; step++) {
            uint32_t ko = step * 32;
            uint32_t ah[2][4], al[2][4];
            #pragma unroll
            for (int mt = 0; mt < 2; mt++) {
                ldsm4(ah[mt], aH + mt * 16 * RB + ko);
                ldsm4(al[mt], aL + mt * 16 * RB + ko);
            }
            #pragma unroll
            for (int p = 0; p < NPAIR; p++) {
                uint32_t bh[4], bl[4];
                ldsm4(bh, bH + p * 16 * RB + ko);
                ldsm4(bl, bL + p * 16 * RB + ko);
                #pragma unroll
                for (int sub = 0; sub < 2; sub++) {
                    uint32_t b0h = bh[sub], b1h = bh[2 + sub];
                    uint32_t b0l = bl[sub], b1l = bl[2 + sub];
                    #pragma unroll
                    for (int mt = 0; mt < 2; mt++) {
                        mma16816(acc[mt][2 * p + sub], ah[mt], b0h, b1h);
                        mma16816(acc[mt][2 * p + sub], ah[mt], b0l, b1l);
                        mma16816(acc[mt][2 * p + sub], al[mt], b0h, b1h);
                    }
                }
            }
        }
        __syncthreads();
        if (kc + 2 < 8) { load_chunk(kc + 2, kc & 1); CPA_COMMIT(); }
    }

    #pragma unroll
    for (int mt = 0; mt < 2; mt++) {
        int rA = row0 + m0 + mt * 16 + g2;
        int rB = rA + 8;
        #pragma unroll
        for (int nt = 0; nt < NTILES; nt++) {
            int cA = col0 + n0 + nt * 8 + 2 * t4;
            #pragma unroll
            for (int j = 0; j < 2; j++) {
                int c = cA + j;
                if (c < Nact) {
                    float v0 = acc[mt][nt][j];
                    float v1 = acc[mt][nt][2 + j];
                    if (mode == 1) {
                        v0 += C[(size_t)rA * ldc + c];
                        v1 += C[(size_t)rB * ldc + c];
                    }
                    C[(size_t)rA * ldc + c] = v0;
                    C[(size_t)rB * ldc + c] = v1;
                }
            }
        }
    }
}

// ---------------- depthwise 3x3x3 conv + SiLU + flip ----------------
__global__ __launch_bounds__(256)
void k_conv(int layer, const float* __restrict__ convb, int ori) {
    int bidx = blockIdx.x;
    int b = bidx >> 8, h = (bidx >> 4) & 15, w = bidx & 15;
    int c = threadIdx.x;
    const float* wt = g_cw + layer * 6912;
    float wr[27];
    #pragma unroll
    for (int j = 0; j < 27; j++) wr[j] = wt[j * 256 + c];
    float bias = convb[c];
    float acc[16];
    #pragma unroll
    for (int d = 0; d < 16; d++) acc[d] = bias;

    #pragma unroll
    for (int s1 = 0; s1 < 3; s1++) {
        int hh = h + s1 - 1; if (hh < 0 || hh > 15) continue;
        #pragma unroll
        for (int s2 = 0; s2 < 3; s2++) {
            int ww = w + s2 - 1; if (ww < 0 || ww > 15) continue;
            size_t cb = ((size_t)(b * LL + (hh * 16 + ww) * 16)) * 512 + c;
            float col[16];
            #pragma unroll
            for (int dd = 0; dd < 16; dd++) col[dd] = g_xz[cb + (size_t)dd * 512];
            float w0 = wr[s1 * 9 + s2 * 3 + 0];
            float w1 = wr[s1 * 9 + s2 * 3 + 1];
            float w2 = wr[s1 * 9 + s2 * 3 + 2];
            #pragma unroll
            for (int d = 0; d < 16; d++) {
                float a = w1 * col[d];
                if (d > 0)  a += w0 * col[d - 1];
                if (d < 15) a += w2 * col[d + 1];
                acc[d] += a;
            }
        }
    }
    int fh = (ori & 1) ? 15 - h : h;
    int fw = (ori & 2) ? 15 - w : w;
    #pragma unroll
    for (int d = 0; d < 16; d++) {
        float sv = acc[d] / (1.f + expf(-acc[d]));
        int fd = (ori & 4) ? 15 - d : d;
        size_t oi = ((size_t)b * LL + (fh * 16 + fw) * 16 + fd) * CC + c;
        split_store(sv, g_ahi, g_alo, oi);
    }
}

// ---------------- FUSED selective scan + gate: phases A+B+C+D ----------------
// grid (NCH=64, 2, BB=2) = 256 blocks x 128 thr; all co-resident (2/SM by smem).
__global__ __launch_bounds__(128)
void k_scanF(int layer, const float* __restrict__ dtw_, const float* __restrict__ dtb_,
             const float* __restrict__ Dv, int ori,
             const float* __restrict__ og, const float* __restrict__ ob) {
    extern __shared__ float sm[];
    float* rvS  = sm;                    // [CLN*128]
    float* dxS  = sm + CLN * 128;
    float* xvS  = sm + 2 * CLN * 128;
    float* Bsm  = sm + 3 * CLN * 128;    // [CLN*16]
    float* Csm  = Bsm + CLN * 16;
    float* dtsm = Csm + CLN * 16;

    int tid = threadIdx.x;
    int c = blockIdx.y * 128 + tid;
    int ch = blockIdx.x, b = blockIdx.z;
    int fast = g_fastA[layer];

    for (int i = tid; i < CLN * 48; i += 128) {
        int t = i / 48, j = i % 48;
        float v = g_dbl[((size_t)b * LL + ch * CLN + t) * 48 + j];
        if (j < 16) dtsm[t * 16 + j] = v;
        else if (j < 32) Bsm[t * 16 + (j - 16)] = v;
        else Csm[t * 16 + (j - 32)] = v;
    }
    __syncthreads();

    float dw[DSZ];
    #pragma unroll
    for (int j = 0; j < DSZ; j++) dw[j] = dtw_[c * DSZ + j];
    float db = dtb_[c];

    // ---- phase A ----
    float h[DSZ], P[DSZ];
    #pragma unroll
    for (int n = 0; n < DSZ; n++) { h[n] = 0.f; P[n] = 1.f; }
    size_t base = ((size_t)b * LL + ch * CLN) * CC + c;
    if (fast) {
        #pragma unroll 4
        for (int t = 0; t < CLN; t++) {
            size_t gi = base + (size_t)t * CC;
            float xv = __bfloat162float(g_ahi[gi]) + __bfloat162float(g_alo[gi]);
            float traw = db;
            #pragma unroll
            for (int j = 0; j < DSZ; j++) traw += dw[j] * dtsm[t * 16 + j];
            float sp = fmaxf(traw, 0.f) + log1pf(expf(-fabsf(traw)));
            float rv = expf(-sp);
            float dtx = sp * xv;
            rvS[t * 128 + tid] = rv;
            dxS[t * 128 + tid] = dtx;
            xvS[t * 128 + tid] = xv;
            float rp[16];
            rpow16(rv, rp);
            #pragma unroll
            for (int n = 0; n < DSZ; n++) {
                h[n] = rp[n] * h[n] + dtx * Bsm[t * 16 + n];
                P[n] *= rp[n];
            }
        }
    } else {
        #pragma unroll 2
        for (int t = 0; t < CLN; t++) {
            size_t gi = base + (size_t)t * CC;
            float xv = __bfloat162float(g_ahi[gi]) + __bfloat162float(g_alo[gi]);
            float traw = db;
            #pragma unroll
            for (int j = 0; j < DSZ; j++) traw += dw[j] * dtsm[t * 16 + j];
            float sp = fmaxf(traw, 0.f) + log1pf(expf(-fabsf(traw)));
            float dtx = sp * xv;
            rvS[t * 128 + tid] = sp;
            dxS[t * 128 + tid] = dtx;
            xvS[t * 128 + tid] = xv;
            #pragma unroll
            for (int n = 0; n < DSZ; n++) {
                float dA = __expf(sp * g_A[((layer * 256) + c) * DSZ + n]);
                h[n] = dA * h[n] + dtx * Bsm[t * 16 + n];
                P[n] *= dA;
            }
        }
    }
    size_t off = (((size_t)(b * CC + c)) * NCH + ch) * DSZ;
    #pragma unroll
    for (int n = 0; n < DSZ; n++) { g_hend[off + n] = h[n]; g_P[off + n] = P[n]; }

    gridbar(0);

    // ---- phase B ----
    {
        int rank = ((blockIdx.z * 2 + blockIdx.y) * NCH + blockIdx.x) * 128 + tid;
        if (rank < BB * CC * DSZ) {
            int n = rank & 15, bc = rank >> 4;
            float H = 0.f;
            size_t bb2 = (size_t)bc * NCH * DSZ + n;
            for (int k0 = 0; k0 < NCH; k0 += 8) {
                float Pv[8], Ev[8];
                #pragma unroll
                for (int q = 0; q < 8; q++) {
                    size_t o = bb2 + (size_t)(k0 + q) * DSZ;
                    Pv[q] = g_P[o];
                    Ev[q] = g_hend[o];
                }
                #pragma unroll
                for (int q = 0; q < 8; q++) {
                    g_hst[bb2 + (size_t)(k0 + q) * DSZ] = H;
                    H = Pv[q] * H + Ev[q];
                }
            }
        }
    }

    gridbar(1);

    // ---- phase C ----
    #pragma unroll
    for (int n = 0; n < DSZ; n++) h[n] = g_hst[off + n];
    float Dc = Dv[c];
    if (fast) {
        #pragma unroll 4
        for (int t = 0; t < CLN; t++) {
            float rv  = rvS[t * 128 + tid];
            float dtx = dxS[t * 128 + tid];
            float xv  = xvS[t * 128 + tid];
            float rp[16];
            rpow16(rv, rp);
            float y = 0.f;
            #pragma unroll
            for (int n = 0; n < DSZ; n++) {
                h[n] = rp[n] * h[n] + dtx * Bsm[t * 16 + n];
                y += h[n] * Csm[t * 16 + n];
            }
            g_y[base + (size_t)t * CC] = y + Dc * xv;
        }
    } else {
        #pragma unroll 2
        for (int t = 0; t < CLN; t++) {
            float sp  = rvS[t * 128 + tid];
            float dtx = dxS[t * 128 + tid];
            float xv  = xvS[t * 128 + tid];
            float y = 0.f;
            #pragma unroll
            for (int n = 0; n < DSZ; n++) {
                float dA = __expf(sp * g_A[((layer * 256) + c) * DSZ + n]);
                h[n] = dA * h[n] + dtx * Bsm[t * 16 + n];
                y += h[n] * Csm[t * 16 + n];
            }
            g_y[base + (size_t)t * CC] = y + Dc * xv;
        }
    }

    gridbar(2);

    // ---- phase D: unflip + output LN + SiLU gate -> splits ----
    {
        int bid = (blockIdx.z * 2 + blockIdx.y) * NCH + blockIdx.x;   // 0..255
        int warp = tid >> 5, lane = tid & 31;
        #pragma unroll
        for (int rr = 0; rr < 8; rr++) {
            int p = bid * 32 + warp * 8 + rr;
            int b2 = p >> 12, l = p & 4095;
            int hh = l >> 8, ww = (l >> 4) & 15, dd = l & 15;
            if (ori & 1) hh = 15 - hh;
            if (ori & 2) ww = 15 - ww;
            if (ori & 4) dd = 15 - dd;
            int ls = (hh << 8) | (ww << 4) | dd;
            const float4* yr = (const float4*)(g_y + ((size_t)((b2 << 12) | ls)) * CC);
            float4 v0 = yr[lane * 2], v1 = yr[lane * 2 + 1];
            float s  = v0.x + v0.y + v0.z + v0.w + v1.x + v1.y + v1.z + v1.w;
            float s2 = v0.x*v0.x + v0.y*v0.y + v0.z*v0.z + v0.w*v0.w
                     + v1.x*v1.x + v1.y*v1.y + v1.z*v1.z + v1.w*v1.w;
            warpRed2(s, s2);
            float m  = s * (1.f / CC);
            float rs = rsqrtf(s2 * (1.f / CC) - m * m + 1e-5f);
            const float4* zr = (const float4*)(g_xz + (size_t)p * 512 + 256);
            float4 z0 = zr[lane * 2], z1 = zr[lane * 2 + 1];
            float4 gg0 = ((const float4*)og)[lane * 2], gg1 = ((const float4*)og)[lane * 2 + 1];
            float4 bb0 = ((const float4*)ob)[lane * 2], bb1 = ((const float4*)ob)[lane * 2 + 1];
            float vv[8] = {v0.x, v0.y, v0.z, v0.w, v1.x, v1.y, v1.z, v1.w};
            float zz[8] = {z0.x, z0.y, z0.z, z0.w, z1.x, z1.y, z1.z, z1.w};
            float ga[8] = {gg0.x, gg0.y, gg0.z, gg0.w, gg1.x, gg1.y, gg1.z, gg1.w};
            float ba[8] = {bb0.x, bb0.y, bb0.z, bb0.w, bb1.x, bb1.y, bb1.z, bb1.w};
            float o[8];
            #pragma unroll
            for (int k = 0; k < 8; k++) {
                float sz = zz[k] / (1.f + expf(-zz[k]));
                o[k] = ((vv[k] - m) * rs * ga[k] + ba[k]) * sz;
            }
            split8_store(o, g_ahi, g_alo, (size_t)p * CC, lane);
        }
    }
}

// ---------------- post-LN stats ----------------
__global__ __launch_bounds__(256)
void k_stats() {
    int warp = threadIdx.x >> 5, lane = threadIdx.x & 31;
    int p = blockIdx.x * 8 + warp;
    const float4* row = (const float4*)(g_t + (size_t)p * CC);
    float4 v0 = row[lane * 2], v1 = row[lane * 2 + 1];
    float s  = v0.x + v0.y + v0.z + v0.w + v1.x + v1.y + v1.z + v1.w;
    float s2 = v0.x*v0.x + v0.y*v0.y + v0.z*v0.z + v0.w*v0.w
             + v1.x*v1.x + v1.y*v1.y + v1.z*v1.z + v1.w*v1.w;
    warpRed2(s, s2);
    if (lane == 0) {
        float m = s * (1.f / CC);
        g_rowm[p] = m;
        g_rowrs[p] = rsqrtf(s2 * (1.f / CC) - m * m + 1e-5f);
    }
}

// ---------------- final transpose + post-LN apply ----------------
__global__ void k_final_tr(float* __restrict__ out,
                           const float* __restrict__ pg, const float* __restrict__ pb) {
    __shared__ float tile[32][33];
    int b = blockIdx.z >> 4, d = blockIdx.z & 15;
    int hw0 = blockIdx.x * 32, c0 = blockIdx.y * 32;
    int tx = threadIdx.x, ty = threadIdx.y;
    int p = b * LL + (hw0 + ty) * 16 + d;
    int c = c0 + tx;
    float v = g_t[(size_t)p * CC + c];
    tile[ty][tx] = (v - g_rowm[p]) * g_rowrs[p] * pg[c] + pb[c];
    __syncthreads();
    out[((size_t)(b * CC + c0 + ty) * 16 + d) * 256 + hw0 + tx] = tile[tx][ty];
}

// ---------------- host ----------------
extern "C" void kernel_launch(void* const* d_in, const int* in_sizes, int n_in,
                              void* d_out, int out_size) {
    const float* x       = (const float*)d_in[0];
    const float* in_w    = (const float*)d_in[1];
    const float* conv_w  = (const float*)d_in[2];
    const float* conv_b  = (const float*)d_in[3];
    const float* xproj_w = (const float*)d_in[4];
    const float* dt_w    = (const float*)d_in[5];
    const float* dt_b    = (const float*)d_in[6];
    const float* A_log   = (const float*)d_in[7];
    const float* D_skip  = (const float*)d_in[8];
    const float* on_g    = (const float*)d_in[9];
    const float* on_b    = (const float*)d_in[10];
    const float* out_w   = (const float*)d_in[11];
    const float* ln1_g   = (const float*)d_in[12];
    const float* ln1_b   = (const float*)d_in[13];
    const float* post_g  = (const float*)d_in[14];
    const float* post_b  = (const float*)d_in[15];
    float* out = (float*)d_out;

    void *p_t, *p_xz, *p_dbl, *p_ahi, *p_alo, *p_whi, *p_wlo;
    cudaGetSymbolAddress(&p_t,   g_t);
    cudaGetSymbolAddress(&p_xz,  g_xz);
    cudaGetSymbolAddress(&p_dbl, g_dbl);
    cudaGetSymbolAddress(&p_ahi, g_ahi);
    cudaGetSymbolAddress(&p_alo, g_alo);
    cudaGetSymbolAddress(&p_whi, g_whi);
    cudaGetSymbolAddress(&p_wlo, g_wlo);
    const uint32_t* whi = (const uint32_t*)p_whi;
    const uint32_t* wlo = (const uint32_t*)p_wlo;

    const int SM64  = 2 * (2 * 128 * 80 + 2 * 64 * 80);        // 61440 B
    const int SMEMF = (3 * CLN * 128 + 3 * CLN * 16) * 4;      // 110592 B
    static int attr_done = 0;
    if (!attr_done) {
        cudaFuncSetAttribute(k_mgemm<64>, cudaFuncAttributeMaxDynamicSharedMemorySize, SM64);
        cudaFuncSetAttribute(k_scanF,     cudaFuncAttributeMaxDynamicSharedMemorySize, SMEMF);
        attr_done = 1;
    }

    k_wsplit_all<<<(WTOT + 255) / 256, 256>>>(in_w, xproj_w, out_w);
    k_cwprep<<<108, 256>>>(conv_w);
    k_prepA_all<<<4, 256>>>(A_log);
    k_init_tr<<<dim3(8, 8, 32), dim3(32, 32)>>>(x);

    for (int i = 0; i < 4; i++) {
        int ori = i;  // i % 8
        k_ln1<<<1024, 256>>>(ln1_g + i * 256, ln1_b + i * 256);
        // in-proj: (8192 x 512)
        k_mgemm<64><<<dim3(8, 64), 256, SM64>>>(
            (const uint32_t*)p_ahi, (const uint32_t*)p_alo,
            whi + WOFF_IN(i) / 2, wlo + WOFF_IN(i) / 2,
            (float*)p_xz, 512, 512, 0);
        k_conv<<<BB * 256, 256>>>(i, conv_b + i * 256, ori);
        // xproj: (8192 x 48)
        k_mgemm<64><<<dim3(1, 64), 256, SM64>>>(
            (const uint32_t*)p_ahi, (const uint32_t*)p_alo,
            whi + WOFF_XP(i) / 2, wlo + WOFF_XP(i) / 2,
            (float*)p_dbl, 48, 48, 0);
        // fused scan (A+B+C) + gate (D)
        k_scanF<<<dim3(NCH, 2, BB), 128, SMEMF>>>(i, dt_w + (size_t)i * 4096,
                                                  dt_b + i * 256, D_skip + i * 256,
                                                  ori, on_g + i * 256, on_b + i * 256);
        // out-proj + residual into t
        k_mgemm<64><<<dim3(4, 64), 256, SM64>>>(
            (const uint32_t*)p_ahi, (const uint32_t*)p_alo,
            whi + WOFF_OUT(i) / 2, wlo + WOFF_OUT(i) / 2,
            (float*)p_t, 256, 256, 1);
    }

    k_stats<<<1024, 256>>>();
    k_final_tr<<<dim3(8, 8, 32), dim3(32, 32)>>>(out, post_g, post_b);
}

// round 13
// speedup vs baseline: 1.0469x; 1.0461x over previous
#include <cuda_runtime.h>
#include <cuda_bf16.h>
#include <math.h>
#include <stdint.h>

#define BB   2
#define CC   256
#define LL   4096
#define DSZ  16
#define NCH  64
#define CLN  64          // LL / NCH
#define NPOS (BB*LL)     // 8192
#define NBLK 128         // fused-scan grid size (1 block/SM, co-resident)

// weight-split buffer layout (bf16 elements)
#define WOFF_IN(i)   ((i) * 131072)
#define WOFF_XP(i)   (524288 + (i) * 16384)
#define WOFF_OUT(i)  (589824 + (i) * 65536)
#define WTOT 851968

// ---------------- scratch ----------------
__device__ float g_t[NPOS*CC];
__device__ float g_xz[NPOS*2*CC];
__device__ float g_dbl[NPOS*48];
__device__ float g_y[NPOS*CC];
__device__ float g_rowm[NPOS];
__device__ float g_rowrs[NPOS];
__device__ float g_A[4*CC*DSZ];
__device__ int   g_fastA[4];
__device__ float g_cw[4*27*CC];
__device__ float g_P[BB*CC*NCH*DSZ];
__device__ float g_hend[BB*CC*NCH*DSZ];
__device__ float g_hst[BB*CC*NCH*DSZ];
__device__ unsigned g_bar[2];            // monotonic grid-barrier tickets
__device__ __nv_bfloat16 g_ahi[NPOS*CC];
__device__ __nv_bfloat16 g_alo[NPOS*CC];
__device__ __nv_bfloat16 g_whi[WTOT];
__device__ __nv_bfloat16 g_wlo[WTOT];

// ---------------- helpers ----------------
__device__ __forceinline__ uint32_t smem_u32(const void* p) {
    uint32_t a;
    asm("{ .reg .u64 t; cvta.to.shared.u64 t, %1; cvt.u32.u64 %0, t; }" : "=r"(a) : "l"(p));
    return a;
}
__device__ __forceinline__ void warpRed2(float& s, float& s2) {
    #pragma unroll
    for (int o = 16; o; o >>= 1) {
        s  += __shfl_xor_sync(0xffffffffu, s,  o);
        s2 += __shfl_xor_sync(0xffffffffu, s2, o);
    }
}
__device__ __forceinline__ uint32_t packbf2(float a, float b) {
    __nv_bfloat162 t = __floats2bfloat162_rn(a, b);
    return *(uint32_t*)&t;
}
__device__ __forceinline__ void split8_store(const float o[8],
                                             __nv_bfloat16* hiB, __nv_bfloat16* loB,
                                             size_t rowoff, int lane) {
    float hf[8], lf[8];
    #pragma unroll
    for (int k = 0; k < 8; k++) {
        __nv_bfloat16 h = __float2bfloat16(o[k]);
        hf[k] = __bfloat162float(h);
        lf[k] = o[k] - hf[k];
    }
    uint4 uh, ul;
    uh.x = packbf2(hf[0], hf[1]); uh.y = packbf2(hf[2], hf[3]);
    uh.z = packbf2(hf[4], hf[5]); uh.w = packbf2(hf[6], hf[7]);
    ul.x = packbf2(lf[0], lf[1]); ul.y = packbf2(lf[2], lf[3]);
    ul.z = packbf2(lf[4], lf[5]); ul.w = packbf2(lf[6], lf[7]);
    ((uint4*)(hiB + rowoff))[lane] = uh;
    ((uint4*)(loB + rowoff))[lane] = ul;
}
__device__ __forceinline__ void split_store(float v, __nv_bfloat16* hi, __nv_bfloat16* lo, size_t i) {
    __nv_bfloat16 h = __float2bfloat16(v);
    hi[i] = h;
    lo[i] = __float2bfloat16(v - __bfloat162float(h));
}
__device__ __forceinline__ void mma16816(float c[4], const uint32_t a[4],
                                         uint32_t b0, uint32_t b1) {
    asm volatile(
        "mma.sync.aligned.m16n8k16.row.col.f32.bf16.bf16.f32 "
        "{%0,%1,%2,%3}, {%4,%5,%6,%7}, {%8,%9}, {%0,%1,%2,%3};"
        : "+f"(c[0]), "+f"(c[1]), "+f"(c[2]), "+f"(c[3])
        : "r"(a[0]), "r"(a[1]), "r"(a[2]), "r"(a[3]), "r"(b0), "r"(b1));
}
__device__ __forceinline__ void ldsm4(uint32_t r[4], uint32_t addr) {
    asm volatile("ldmatrix.sync.aligned.m8n8.x4.shared.b16 {%0,%1,%2,%3}, [%4];"
        : "=r"(r[0]), "=r"(r[1]), "=r"(r[2]), "=r"(r[3]) : "r"(addr));
}
__device__ __forceinline__ void cpa16(uint32_t saddr, const void* g) {
    asm volatile("cp.async.cg.shared.global [%0], [%1], 16;" :: "r"(saddr), "l"(g));
}
#define CPA_COMMIT() asm volatile("cp.async.commit_group;" ::: "memory")
#define CPA_WAIT(N)  asm volatile("cp.async.wait_group %0;" :: "n"(N) : "memory")

// r^1..r^16 via log-depth tree
__device__ __forceinline__ void rpow16(float rv, float rp[16]) {
    float r2 = rv * rv, r4 = r2 * r2, r8 = r4 * r4;
    rp[0] = rv;        rp[1] = r2;        rp[2] = r2 * rv;   rp[3] = r4;
    rp[4] = r4 * rv;   rp[5] = r4 * r2;   rp[6] = r4 * rp[2]; rp[7] = r8;
    rp[8] = r8 * rv;   rp[9] = r8 * r2;   rp[10] = r8 * rp[2]; rp[11] = r8 * r4;
    rp[12] = r8 * rp[4]; rp[13] = r8 * rp[5]; rp[14] = r8 * rp[6]; rp[15] = r8 * r8;
}

// monotonic-ticket grid barrier (all NBLK blocks co-resident; graph-replay safe)
__device__ __forceinline__ void gridbar(int slot) {
    __syncthreads();
    if (threadIdx.x == 0) {
        __threadfence();
        unsigned ticket = atomicAdd(&g_bar[slot], 1u) + 1u;
        unsigned target = ((ticket - 1u) / NBLK + 1u) * NBLK;
        while ((int)(*(volatile unsigned*)&g_bar[slot] - target) < 0) { }
        __threadfence();
    }
    __syncthreads();
}

// ---------------- all-layer weight split ----------------
__global__ void k_wsplit_all(const float* __restrict__ inw,
                             const float* __restrict__ xpw,
                             const float* __restrict__ ow) {
    int idx = blockIdx.x * 256 + threadIdx.x;
    if (idx >= WTOT) return;
    float v;
    if (idx < 524288) {
        v = inw[idx];
    } else if (idx < 589824) {
        int rel = idx - 524288;
        int layer = rel >> 14, w = rel & 16383;
        int row = w >> 8, col = w & 255;
        v = (row < 48) ? xpw[layer * 12288 + row * 256 + col] : 0.f;
    } else {
        v = ow[idx - 589824];
    }
    split_store(v, g_whi, g_wlo, idx);
}

// ---------------- conv weight transpose ----------------
__global__ void k_cwprep(const float* __restrict__ cw) {
    int idx = blockIdx.x * 256 + threadIdx.x;
    if (idx >= 4 * 27 * 256) return;
    int layer = idx / 6912, rem = idx % 6912;
    int j = rem >> 8, c = rem & 255;
    g_cw[idx] = cw[layer * 6912 + c * 27 + j];
}

// ---------------- all-layer A prep ----------------
__global__ void k_prepA_all(const float* __restrict__ alog) {
    int layer = blockIdx.x, c = threadIdx.x;
    __shared__ int ok;
    if (c == 0) ok = 1;
    __syncthreads();
    bool good = true;
    #pragma unroll
    for (int n = 0; n < DSZ; n++) {
        float a = -expf(alog[(layer * 256 + c) * DSZ + n]);
        g_A[(layer * 256 + c) * DSZ + n] = a;
        if (fabsf(a + (float)(n + 1)) > 1e-3f) good = false;
    }
    if (!good) atomicAnd(&ok, 0);
    __syncthreads();
    if (c == 0) g_fastA[layer] = ok;
}

// ---------------- initial transpose ----------------
__global__ void k_init_tr(const float* __restrict__ x) {
    __shared__ float tile[32][33];
    int b = blockIdx.z >> 4, d = blockIdx.z & 15;
    int hw0 = blockIdx.x * 32, c0 = blockIdx.y * 32;
    int tx = threadIdx.x, ty = threadIdx.y;
    tile[ty][tx] = x[((size_t)(b*CC + c0 + ty) * 16 + d) * 256 + hw0 + tx];
    __syncthreads();
    g_t[((size_t)b*LL + (size_t)(hw0 + ty) * 16 + d) * CC + c0 + tx] = tile[tx][ty];
}

// ---------------- LN1 (warp per row) + bf16 split ----------------
__global__ __launch_bounds__(256)
void k_ln1(const float* __restrict__ g, const float* __restrict__ bvec) {
    int warp = threadIdx.x >> 5, lane = threadIdx.x & 31;
    int p = blockIdx.x * 8 + warp;
    const float4* row = (const float4*)(g_t + (size_t)p * CC);
    float4 v0 = row[lane * 2], v1 = row[lane * 2 + 1];
    float s  = v0.x + v0.y + v0.z + v0.w + v1.x + v1.y + v1.z + v1.w;
    float s2 = v0.x*v0.x + v0.y*v0.y + v0.z*v0.z + v0.w*v0.w
             + v1.x*v1.x + v1.y*v1.y + v1.z*v1.z + v1.w*v1.w;
    warpRed2(s, s2);
    float m  = s * (1.f / CC);
    float rs = rsqrtf(s2 * (1.f / CC) - m * m + 1e-5f);
    float4 gg0 = ((const float4*)g)[lane * 2],    gg1 = ((const float4*)g)[lane * 2 + 1];
    float4 bb0 = ((const float4*)bvec)[lane * 2], bb1 = ((const float4*)bvec)[lane * 2 + 1];
    float o[8];
    o[0] = (v0.x - m) * rs * gg0.x + bb0.x;  o[1] = (v0.y - m) * rs * gg0.y + bb0.y;
    o[2] = (v0.z - m) * rs * gg0.z + bb0.z;  o[3] = (v0.w - m) * rs * gg0.w + bb0.w;
    o[4] = (v1.x - m) * rs * gg1.x + bb1.x;  o[5] = (v1.y - m) * rs * gg1.y + bb1.y;
    o[6] = (v1.z - m) * rs * gg1.z + bb1.z;  o[7] = (v1.w - m) * rs * gg1.w + bb1.w;
    split8_store(o, g_ahi, g_alo, (size_t)p * CC, lane);
}

// ---------------- pipelined ldmatrix bf16x3 GEMM (pristine R10 form) ----------------
template<int NT>
__global__ __launch_bounds__(256, 3)
void k_mgemm(const uint32_t* __restrict__ Ahi, const uint32_t* __restrict__ Alo,
             const uint32_t* __restrict__ Bhi, const uint32_t* __restrict__ Blo,
             float* __restrict__ C, int ldc, int Nact, int mode) {
    constexpr int RB = 80;
    constexpr int AL_OFF = 128 * RB;
    constexpr int BH_OFF = 2 * 128 * RB;
    constexpr int BL_OFF = BH_OFF + NT * RB;
    constexpr int STAGE  = BH_OFF + 2 * NT * RB;
    constexpr int NTILES = NT / 16;
    constexpr int NPAIR  = NTILES / 2;

    extern __shared__ __align__(16) char smem[];
    uint32_t sbase = smem_u32(smem);
    int tid = threadIdx.x, wid = tid >> 5, lane = tid & 31;
    int g2 = lane >> 2, t4 = lane & 3;
    int row0 = blockIdx.y * 128, col0 = blockIdx.x * NT;
    int m0 = (wid >> 1) * 32, n0 = (wid & 1) * (NT / 2);
    uint32_t lmo = (uint32_t)(((lane & 7) + ((lane >> 3) & 1) * 8) * RB + (lane >> 4) * 16);

    float acc[2][NTILES][4];
    #pragma unroll
    for (int mt = 0; mt < 2; mt++)
        #pragma unroll
        for (int nt = 0; nt < NTILES; nt++)
            #pragma unroll
            for (int j = 0; j < 4; j++) acc[mt][nt][j] = 0.f;

    int lr = tid >> 2, lc4 = (tid & 3) * 4;

    auto load_chunk = [&](int kc, int stg) {
        uint32_t sb = sbase + stg * STAGE;
        int kw = kc * 16;
        #pragma unroll
        for (int i = 0; i < 2; i++) {
            int r = lr + i * 64;
            size_t gi = (size_t)(row0 + r) * 128 + kw + lc4;
            uint32_t so = (uint32_t)(r * RB + lc4 * 4);
            cpa16(sb + so,          Ahi + gi);
            cpa16(sb + AL_OFF + so, Alo + gi);
        }
        #pragma unroll
        for (int i = 0; i < NT / 64; i++) {
            int r = lr + i * 64;
            size_t gi = (size_t)(col0 + r) * 128 + kw + lc4;
            uint32_t so = (uint32_t)(r * RB + lc4 * 4);
            cpa16(sb + BH_OFF + so, Bhi + gi);
            cpa16(sb + BL_OFF + so, Blo + gi);
        }
    };

    load_chunk(0, 0); CPA_COMMIT();
    load_chunk(1, 1); CPA_COMMIT();

    #pragma unroll 1
    for (int kc = 0; kc < 8; kc++) {
        if (kc < 7) { CPA_WAIT(1); } else { CPA_WAIT(0); }
        __syncthreads();
        uint32_t sb = sbase + (kc & 1) * STAGE;
        uint32_t aH = sb + m0 * RB + lmo;
        uint32_t aL = aH + AL_OFF;
        uint32_t bH = sb + BH_OFF + n0 * RB + lmo;
        uint32_t bL = bH + NT * RB;
        #pragma unroll
        for (int step = 0; step < 2; step++) {
            uint32_t ko = step * 32;
            uint32_t ah[2][4], al[2][4];
            #pragma unroll
            for (int mt = 0; mt < 2; mt++) {
                ldsm4(ah[mt], aH + mt * 16 * RB + ko);
                ldsm4(al[mt], aL + mt * 16 * RB + ko);
            }
            #pragma unroll
            for (int p = 0; p < NPAIR; p++) {
                uint32_t bh[4], bl[4];
                ldsm4(bh, bH + p * 16 * RB + ko);
                ldsm4(bl, bL + p * 16 * RB + ko);
                #pragma unroll
                for (int sub = 0; sub < 2; sub++) {
                    uint32_t b0h = bh[sub], b1h = bh[2 + sub];
                    uint32_t b0l = bl[sub], b1l = bl[2 + sub];
                    #pragma unroll
                    for (int mt = 0; mt < 2; mt++) {
                        mma16816(acc[mt][2 * p + sub], ah[mt], b0h, b1h);
                        mma16816(acc[mt][2 * p + sub], ah[mt], b0l, b1l);
                        mma16816(acc[mt][2 * p + sub], al[mt], b0h, b1h);
                    }
                }
            }
        }
        __syncthreads();
        if (kc + 2 < 8) { load_chunk(kc + 2, kc & 1); CPA_COMMIT(); }
    }

    #pragma unroll
    for (int mt = 0; mt < 2; mt++) {
        int rA = row0 + m0 + mt * 16 + g2;
        int rB = rA + 8;
        #pragma unroll
        for (int nt = 0; nt < NTILES; nt++) {
            int cA = col0 + n0 + nt * 8 + 2 * t4;
            #pragma unroll
            for (int j = 0; j < 2; j++) {
                int c = cA + j;
                if (c < Nact) {
                    float v0 = acc[mt][nt][j];
                    float v1 = acc[mt][nt][2 + j];
                    if (mode == 1) {
                        v0 += C[(size_t)rA * ldc + c];
                        v1 += C[(size_t)rB * ldc + c];
                    }
                    C[(size_t)rA * ldc + c] = v0;
                    C[(size_t)rB * ldc + c] = v1;
                }
            }
        }
    }
}

// ---------------- depthwise 3x3x3 conv + SiLU + flip ----------------
__global__ __launch_bounds__(256)
void k_conv(int layer, const float* __restrict__ convb, int ori) {
    int bidx = blockIdx.x;
    int b = bidx >> 8, h = (bidx >> 4) & 15, w = bidx & 15;
    int c = threadIdx.x;
    const float* wt = g_cw + layer * 6912;
    float wr[27];
    #pragma unroll
    for (int j = 0; j < 27; j++) wr[j] = wt[j * 256 + c];
    float bias = convb[c];
    float acc[16];
    #pragma unroll
    for (int d = 0; d < 16; d++) acc[d] = bias;

    #pragma unroll
    for (int s1 = 0; s1 < 3; s1++) {
        int hh = h + s1 - 1; if (hh < 0 || hh > 15) continue;
        #pragma unroll
        for (int s2 = 0; s2 < 3; s2++) {
            int ww = w + s2 - 1; if (ww < 0 || ww > 15) continue;
            size_t cb = ((size_t)(b * LL + (hh * 16 + ww) * 16)) * 512 + c;
            float col[16];
            #pragma unroll
            for (int dd = 0; dd < 16; dd++) col[dd] = g_xz[cb + (size_t)dd * 512];
            float w0 = wr[s1 * 9 + s2 * 3 + 0];
            float w1 = wr[s1 * 9 + s2 * 3 + 1];
            float w2 = wr[s1 * 9 + s2 * 3 + 2];
            #pragma unroll
            for (int d = 0; d < 16; d++) {
                float a = w1 * col[d];
                if (d > 0)  a += w0 * col[d - 1];
                if (d < 15) a += w2 * col[d + 1];
                acc[d] += a;
            }
        }
    }
    int fh = (ori & 1) ? 15 - h : h;
    int fw = (ori & 2) ? 15 - w : w;
    #pragma unroll
    for (int d = 0; d < 16; d++) {
        float sv = acc[d] / (1.f + expf(-acc[d]));
        int fd = (ori & 4) ? 15 - d : d;
        size_t oi = ((size_t)b * LL + (fh * 16 + fw) * 16 + fd) * CC + c;
        split_store(sv, g_ahi, g_alo, oi);
    }
}

// ---------------- FUSED selective scan: phases A+B+C, 128 blocks x 256 thr ----------------
// grid (NCH=64, 1, BB=2) = 128 blocks; 1 block/SM (204KB smem), all co-resident.
__global__ __launch_bounds__(256)
void k_scanF(int layer, const float* __restrict__ dtw_, const float* __restrict__ dtb_,
             const float* __restrict__ Dv) {
    extern __shared__ float sm[];
    float* rvS  = sm;                    // [CLN*256] rv (fast) or sp (generic)
    float* dxS  = sm + CLN * 256;        // [CLN*256] dtx
    float* xvS  = sm + 2 * CLN * 256;    // [CLN*256] xv
    float* Bsm  = sm + 3 * CLN * 256;    // [CLN*16]
    float* Csm  = Bsm + CLN * 16;        // [CLN*16]
    float* dtsm = Csm + CLN * 16;        // [CLN*16]

    int tid = threadIdx.x;
    int c = tid;                          // full 256-channel slab per block
    int ch = blockIdx.x, b = blockIdx.z;
    int fast = g_fastA[layer];

    for (int i = tid; i < CLN * 48; i += 256) {
        int t = i / 48, j = i % 48;
        float v = g_dbl[((size_t)b * LL + ch * CLN + t) * 48 + j];
        if (j < 16) dtsm[t * 16 + j] = v;
        else if (j < 32) Bsm[t * 16 + (j - 16)] = v;
        else Csm[t * 16 + (j - 32)] = v;
    }
    __syncthreads();

    float dw[DSZ];
    #pragma unroll
    for (int j = 0; j < DSZ; j++) dw[j] = dtw_[c * DSZ + j];
    float db = dtb_[c];

    // ---- phase A ----
    float h[DSZ], P[DSZ];
    #pragma unroll
    for (int n = 0; n < DSZ; n++) { h[n] = 0.f; P[n] = 1.f; }
    size_t base = ((size_t)b * LL + ch * CLN) * CC + c;
    if (fast) {
        #pragma unroll 4
        for (int t = 0; t < CLN; t++) {
            size_t gi = base + (size_t)t * CC;
            float xv = __bfloat162float(g_ahi[gi]) + __bfloat162float(g_alo[gi]);
            float traw = db;
            #pragma unroll
            for (int j = 0; j < DSZ; j++) traw += dw[j] * dtsm[t * 16 + j];
            float sp = fmaxf(traw, 0.f) + log1pf(expf(-fabsf(traw)));
            float rv = expf(-sp);
            float dtx = sp * xv;
            rvS[t * 256 + tid] = rv;
            dxS[t * 256 + tid] = dtx;
            xvS[t * 256 + tid] = xv;
            float rp[16];
            rpow16(rv, rp);
            #pragma unroll
            for (int n = 0; n < DSZ; n++) {
                h[n] = rp[n] * h[n] + dtx * Bsm[t * 16 + n];
                P[n] *= rp[n];
            }
        }
    } else {
        #pragma unroll 2
        for (int t = 0; t < CLN; t++) {
            size_t gi = base + (size_t)t * CC;
            float xv = __bfloat162float(g_ahi[gi]) + __bfloat162float(g_alo[gi]);
            float traw = db;
            #pragma unroll
            for (int j = 0; j < DSZ; j++) traw += dw[j] * dtsm[t * 16 + j];
            float sp = fmaxf(traw, 0.f) + log1pf(expf(-fabsf(traw)));
            float dtx = sp * xv;
            rvS[t * 256 + tid] = sp;
            dxS[t * 256 + tid] = dtx;
            xvS[t * 256 + tid] = xv;
            #pragma unroll
            for (int n = 0; n < DSZ; n++) {
                float dA = __expf(sp * g_A[((layer * 256) + c) * DSZ + n]);
                h[n] = dA * h[n] + dtx * Bsm[t * 16 + n];
                P[n] *= dA;
            }
        }
    }
    size_t off = (((size_t)(b * CC + c)) * NCH + ch) * DSZ;
    #pragma unroll
    for (int n = 0; n < DSZ; n++) { g_hend[off + n] = h[n]; g_P[off + n] = P[n]; }

    gridbar(0);

    // ---- phase B: sequential chunk combine (first 8192 global threads) ----
    {
        int rank = (blockIdx.z * NCH + blockIdx.x) * 256 + tid;
        if (rank < BB * CC * DSZ) {
            int n = rank & 15, bc = rank >> 4;
            float H = 0.f;
            size_t bb2 = (size_t)bc * NCH * DSZ + n;
            for (int k0 = 0; k0 < NCH; k0 += 8) {
                float Pv[8], Ev[8];
                #pragma unroll
                for (int q = 0; q < 8; q++) {
                    size_t o = bb2 + (size_t)(k0 + q) * DSZ;
                    Pv[q] = g_P[o];
                    Ev[q] = g_hend[o];
                }
                #pragma unroll
                for (int q = 0; q < 8; q++) {
                    g_hst[bb2 + (size_t)(k0 + q) * DSZ] = H;
                    H = Pv[q] * H + Ev[q];
                }
            }
        }
    }

    gridbar(1);

    // ---- phase C ----
    #pragma unroll
    for (int n = 0; n < DSZ; n++) h[n] = g_hst[off + n];
    float Dc = Dv[c];
    if (fast) {
        #pragma unroll 4
        for (int t = 0; t < CLN; t++) {
            float rv  = rvS[t * 256 + tid];
            float dtx = dxS[t * 256 + tid];
            float xv  = xvS[t * 256 + tid];
            float rp[16];
            rpow16(rv, rp);
            float y = 0.f;
            #pragma unroll
            for (int n = 0; n < DSZ; n++) {
                h[n] = rp[n] * h[n] + dtx * Bsm[t * 16 + n];
                y += h[n] * Csm[t * 16 + n];
            }
            g_y[base + (size_t)t * CC] = y + Dc * xv;
        }
    } else {
        #pragma unroll 2
        for (int t = 0; t < CLN; t++) {
            float sp  = rvS[t * 256 + tid];
            float dtx = dxS[t * 256 + tid];
            float xv  = xvS[t * 256 + tid];
            float y = 0.f;
            #pragma unroll
            for (int n = 0; n < DSZ; n++) {
                float dA = __expf(sp * g_A[((layer * 256) + c) * DSZ + n]);
                h[n] = dA * h[n] + dtx * Bsm[t * 16 + n];
                y += h[n] * Csm[t * 16 + n];
            }
            g_y[base + (size_t)t * CC] = y + Dc * xv;
        }
    }
}

// ---------------- unflip + output LN + SiLU gate ----------------
__global__ __launch_bounds__(256)
void k_gate(const float* __restrict__ og, const float* __restrict__ ob, int ori) {
    int warp = threadIdx.x >> 5, lane = threadIdx.x & 31;
    int p = blockIdx.x * 8 + warp;
    int b = p >> 12, l = p & 4095;
    int h = l >> 8, w = (l >> 4) & 15, d = l & 15;
    if (ori & 1) h = 15 - h;
    if (ori & 2) w = 15 - w;
    if (ori & 4) d = 15 - d;
    int ls = (h << 8) | (w << 4) | d;
    const float4* yr = (const float4*)(g_y + ((size_t)((b << 12) | ls)) * CC);
    float4 v0 = yr[lane * 2], v1 = yr[lane * 2 + 1];
    float s  = v0.x + v0.y + v0.z + v0.w + v1.x + v1.y + v1.z + v1.w;
    float s2 = v0.x*v0.x + v0.y*v0.y + v0.z*v0.z + v0.w*v0.w
             + v1.x*v1.x + v1.y*v1.y + v1.z*v1.z + v1.w*v1.w;
    warpRed2(s, s2);
    float m  = s * (1.f / CC);
    float rs = rsqrtf(s2 * (1.f / CC) - m * m + 1e-5f);
    const float4* zr = (const float4*)(g_xz + (size_t)p * 512 + 256);
    float4 z0 = zr[lane * 2], z1 = zr[lane * 2 + 1];
    float4 gg0 = ((const float4*)og)[lane * 2], gg1 = ((const float4*)og)[lane * 2 + 1];
    float4 bb0 = ((const float4*)ob)[lane * 2], bb1 = ((const float4*)ob)[lane * 2 + 1];
    float vv[8] = {v0.x, v0.y, v0.z, v0.w, v1.x, v1.y, v1.z, v1.w};
    float zz[8] = {z0.x, z0.y, z0.z, z0.w, z1.x, z1.y, z1.z, z1.w};
    float ga[8] = {gg0.x, gg0.y, gg0.z, gg0.w, gg1.x, gg1.y, gg1.z, gg1.w};
    float ba[8] = {bb0.x, bb0.y, bb0.z, bb0.w, bb1.x, bb1.y, bb1.z, bb1.w};
    float o[8];
    #pragma unroll
    for (int k = 0; k < 8; k++) {
        float sz = zz[k] / (1.f + expf(-zz[k]));
        o[k] = ((vv[k] - m) * rs * ga[k] + ba[k]) * sz;
    }
    split8_store(o, g_ahi, g_alo, (size_t)p * CC, lane);
}

// ---------------- post-LN stats ----------------
__global__ __launch_bounds__(256)
void k_stats() {
    int warp = threadIdx.x >> 5, lane = threadIdx.x & 31;
    int p = blockIdx.x * 8 + warp;
    const float4* row = (const float4*)(g_t + (size_t)p * CC);
    float4 v0 = row[lane * 2], v1 = row[lane * 2 + 1];
    float s  = v0.x + v0.y + v0.z + v0.w + v1.x + v1.y + v1.z + v1.w;
    float s2 = v0.x*v0.x + v0.y*v0.y + v0.z*v0.z + v0.w*v0.w
             + v1.x*v1.x + v1.y*v1.y + v1.z*v1.z + v1.w*v1.w;
    warpRed2(s, s2);
    if (lane == 0) {
        float m = s * (1.f / CC);
        g_rowm[p] = m;
        g_rowrs[p] = rsqrtf(s2 * (1.f / CC) - m * m + 1e-5f);
    }
}

// ---------------- final transpose + post-LN apply ----------------
__global__ void k_final_tr(float* __restrict__ out,
                           const float* __restrict__ pg, const float* __restrict__ pb) {
    __shared__ float tile[32][33];
    int b = blockIdx.z >> 4, d = blockIdx.z & 15;
    int hw0 = blockIdx.x * 32, c0 = blockIdx.y * 32;
    int tx = threadIdx.x, ty = threadIdx.y;
    int p = b * LL + (hw0 + ty) * 16 + d;
    int c = c0 + tx;
    float v = g_t[(size_t)p * CC + c];
    tile[ty][tx] = (v - g_rowm[p]) * g_rowrs[p] * pg[c] + pb[c];
    __syncthreads();
    out[((size_t)(b * CC + c0 + ty) * 16 + d) * 256 + hw0 + tx] = tile[tx][ty];
}

// ---------------- host ----------------
extern "C" void kernel_launch(void* const* d_in, const int* in_sizes, int n_in,
                              void* d_out, int out_size) {
    const float* x       = (const float*)d_in[0];
    const float* in_w    = (const float*)d_in[1];
    const float* conv_w  = (const float*)d_in[2];
    const float* conv_b  = (const float*)d_in[3];
    const float* xproj_w = (const float*)d_in[4];
    const float* dt_w    = (const float*)d_in[5];
    const float* dt_b    = (const float*)d_in[6];
    const float* A_log   = (const float*)d_in[7];
    const float* D_skip  = (const float*)d_in[8];
    const float* on_g    = (const float*)d_in[9];
    const float* on_b    = (const float*)d_in[10];
    const float* out_w   = (const float*)d_in[11];
    const float* ln1_g   = (const float*)d_in[12];
    const float* ln1_b   = (const float*)d_in[13];
    const float* post_g  = (const float*)d_in[14];
    const float* post_b  = (const float*)d_in[15];
    float* out = (float*)d_out;

    void *p_t, *p_xz, *p_dbl, *p_ahi, *p_alo, *p_whi, *p_wlo;
    cudaGetSymbolAddress(&p_t,   g_t);
    cudaGetSymbolAddress(&p_xz,  g_xz);
    cudaGetSymbolAddress(&p_dbl, g_dbl);
    cudaGetSymbolAddress(&p_ahi, g_ahi);
    cudaGetSymbolAddress(&p_alo, g_alo);
    cudaGetSymbolAddress(&p_whi, g_whi);
    cudaGetSymbolAddress(&p_wlo, g_wlo);
    const uint32_t* whi = (const uint32_t*)p_whi;
    const uint32_t* wlo = (const uint32_t*)p_wlo;

    const int SM64  = 2 * (2 * 128 * 80 + 2 * 64 * 80);        // 61440 B
    const int SMEMF = (3 * CLN * 256 + 3 * CLN * 16) * 4;      // 208896 B
    static int attr_done = 0;
    if (!attr_done) {
        cudaFuncSetAttribute(k_mgemm<64>, cudaFuncAttributeMaxDynamicSharedMemorySize, SM64);
        cudaFuncSetAttribute(k_scanF,     cudaFuncAttributeMaxDynamicSharedMemorySize, SMEMF);
        attr_done = 1;
    }

    k_wsplit_all<<<(WTOT + 255) / 256, 256>>>(in_w, xproj_w, out_w);
    k_cwprep<<<108, 256>>>(conv_w);
    k_prepA_all<<<4, 256>>>(A_log);
    k_init_tr<<<dim3(8, 8, 32), dim3(32, 32)>>>(x);

    for (int i = 0; i < 4; i++) {
        int ori = i;  // i % 8
        k_ln1<<<1024, 256>>>(ln1_g + i * 256, ln1_b + i * 256);
        // in-proj: (8192 x 512)
        k_mgemm<64><<<dim3(8, 64), 256, SM64>>>(
            (const uint32_t*)p_ahi, (const uint32_t*)p_alo,
            whi + WOFF_IN(i) / 2, wlo + WOFF_IN(i) / 2,
            (float*)p_xz, 512, 512, 0);
        k_conv<<<BB * 256, 256>>>(i, conv_b + i * 256, ori);
        // xproj: (8192 x 48)
        k_mgemm<64><<<dim3(1, 64), 256, SM64>>>(
            (const uint32_t*)p_ahi, (const uint32_t*)p_alo,
            whi + WOFF_XP(i) / 2, wlo + WOFF_XP(i) / 2,
            (float*)p_dbl, 48, 48, 0);
        // fused scan (A+B+C), 128 balanced blocks
        k_scanF<<<dim3(NCH, 1, BB), 256, SMEMF>>>(i, dt_w + (size_t)i * 4096,
                                                  dt_b + i * 256, D_skip + i * 256);
        k_gate<<<1024, 256>>>(on_g + i * 256, on_b + i * 256, ori);
        // out-proj + residual into t
        k_mgemm<64><<<dim3(4, 64), 256, SM64>>>(
            (const uint32_t*)p_ahi, (const uint32_t*)p_alo,
            whi + WOFF_OUT(i) / 2, wlo + WOFF_OUT(i) / 2,
            (float*)p_t, 256, 256, 1);
    }

    k_stats<<<1024, 256>>>();
    k_final_tr<<<dim3(8, 8, 32), dim3(32, 32)>>>(out, post_g, post_b);
}

// round 14
// speedup vs baseline: 1.0569x; 1.0095x over previous
#include <cuda_runtime.h>
#include <cuda_bf16.h>
#include <math.h>
#include <stdint.h>

#define BB   2
#define CC   256
#define LL   4096
#define DSZ  16
#define NCH  64
#define CLN  64          // LL / NCH
#define NPOS (BB*LL)     // 8192
#define NBLK 128         // fused-scan grid size (1 block/SM, co-resident)

// weight-split buffer layout (bf16 elements)
#define WOFF_IN(i)   ((i) * 131072)
#define WOFF_XP(i)   (524288 + (i) * 16384)
#define WOFF_OUT(i)  (589824 + (i) * 65536)
#define WTOT 851968

// ---------------- scratch ----------------
__device__ float g_t[NPOS*CC];
__device__ float g_xz[NPOS*2*CC];
__device__ float g_dbl[NPOS*48];
__device__ float g_rowm[NPOS];
__device__ float g_rowrs[NPOS];
__device__ float g_A[4*CC*DSZ];
__device__ int   g_fastA[4];
__device__ float g_cw[4*27*CC];
__device__ float g_P[BB*CC*NCH*DSZ];
__device__ float g_hend[BB*CC*NCH*DSZ];
__device__ float g_hst[BB*CC*NCH*DSZ];
__device__ unsigned g_bar[2];            // monotonic grid-barrier tickets
__device__ __nv_bfloat16 g_ahi[NPOS*CC];
__device__ __nv_bfloat16 g_alo[NPOS*CC];
__device__ __nv_bfloat16 g_whi[WTOT];
__device__ __nv_bfloat16 g_wlo[WTOT];

// ---------------- helpers ----------------
__device__ __forceinline__ uint32_t smem_u32(const void* p) {
    uint32_t a;
    asm("{ .reg .u64 t; cvta.to.shared.u64 t, %1; cvt.u32.u64 %0, t; }" : "=r"(a) : "l"(p));
    return a;
}
__device__ __forceinline__ void warpRed2(float& s, float& s2) {
    #pragma unroll
    for (int o = 16; o; o >>= 1) {
        s  += __shfl_xor_sync(0xffffffffu, s,  o);
        s2 += __shfl_xor_sync(0xffffffffu, s2, o);
    }
}
__device__ __forceinline__ uint32_t packbf2(float a, float b) {
    __nv_bfloat162 t = __floats2bfloat162_rn(a, b);
    return *(uint32_t*)&t;
}
__device__ __forceinline__ void split8_store(const float o[8],
                                             __nv_bfloat16* hiB, __nv_bfloat16* loB,
                                             size_t rowoff, int lane) {
    float hf[8], lf[8];
    #pragma unroll
    for (int k = 0; k < 8; k++) {
        __nv_bfloat16 h = __float2bfloat16(o[k]);
        hf[k] = __bfloat162float(h);
        lf[k] = o[k] - hf[k];
    }
    uint4 uh, ul;
    uh.x = packbf2(hf[0], hf[1]); uh.y = packbf2(hf[2], hf[3]);
    uh.z = packbf2(hf[4], hf[5]); uh.w = packbf2(hf[6], hf[7]);
    ul.x = packbf2(lf[0], lf[1]); ul.y = packbf2(lf[2], lf[3]);
    ul.z = packbf2(lf[4], lf[5]); ul.w = packbf2(lf[6], lf[7]);
    ((uint4*)(hiB + rowoff))[lane] = uh;
    ((uint4*)(loB + rowoff))[lane] = ul;
}
__device__ __forceinline__ void split_store(float v, __nv_bfloat16* hi, __nv_bfloat16* lo, size_t i) {
    __nv_bfloat16 h = __float2bfloat16(v);
    hi[i] = h;
    lo[i] = __float2bfloat16(v - __bfloat162float(h));
}
__device__ __forceinline__ void mma16816(float c[4], const uint32_t a[4],
                                         uint32_t b0, uint32_t b1) {
    asm volatile(
        "mma.sync.aligned.m16n8k16.row.col.f32.bf16.bf16.f32 "
        "{%0,%1,%2,%3}, {%4,%5,%6,%7}, {%8,%9}, {%0,%1,%2,%3};"
        : "+f"(c[0]), "+f"(c[1]), "+f"(c[2]), "+f"(c[3])
        : "r"(a[0]), "r"(a[1]), "r"(a[2]), "r"(a[3]), "r"(b0), "r"(b1));
}
__device__ __forceinline__ void ldsm4(uint32_t r[4], uint32_t addr) {
    asm volatile("ldmatrix.sync.aligned.m8n8.x4.shared.b16 {%0,%1,%2,%3}, [%4];"
        : "=r"(r[0]), "=r"(r[1]), "=r"(r[2]), "=r"(r[3]) : "r"(addr));
}
__device__ __forceinline__ void cpa16(uint32_t saddr, const void* g) {
    asm volatile("cp.async.cg.shared.global [%0], [%1], 16;" :: "r"(saddr), "l"(g));
}
#define CPA_COMMIT() asm volatile("cp.async.commit_group;" ::: "memory")
#define CPA_WAIT(N)  asm volatile("cp.async.wait_group %0;" :: "n"(N) : "memory")

// r^1..r^16 via log-depth tree
__device__ __forceinline__ void rpow16(float rv, float rp[16]) {
    float r2 = rv * rv, r4 = r2 * r2, r8 = r4 * r4;
    rp[0] = rv;        rp[1] = r2;        rp[2] = r2 * rv;   rp[3] = r4;
    rp[4] = r4 * rv;   rp[5] = r4 * r2;   rp[6] = r4 * rp[2]; rp[7] = r8;
    rp[8] = r8 * rv;   rp[9] = r8 * r2;   rp[10] = r8 * rp[2]; rp[11] = r8 * r4;
    rp[12] = r8 * rp[4]; rp[13] = r8 * rp[5]; rp[14] = r8 * rp[6]; rp[15] = r8 * r8;
}

// monotonic-ticket grid barrier (all NBLK blocks co-resident; graph-replay safe)
__device__ __forceinline__ void gridbar(int slot) {
    __syncthreads();
    if (threadIdx.x == 0) {
        __threadfence();
        unsigned ticket = atomicAdd(&g_bar[slot], 1u) + 1u;
        unsigned target = ((ticket - 1u) / NBLK + 1u) * NBLK;
        while ((int)(*(volatile unsigned*)&g_bar[slot] - target) < 0) { }
        __threadfence();
    }
    __syncthreads();
}

// ---------------- all-layer weight split ----------------
__global__ void k_wsplit_all(const float* __restrict__ inw,
                             const float* __restrict__ xpw,
                             const float* __restrict__ ow) {
    int idx = blockIdx.x * 256 + threadIdx.x;
    if (idx >= WTOT) return;
    float v;
    if (idx < 524288) {
        v = inw[idx];
    } else if (idx < 589824) {
        int rel = idx - 524288;
        int layer = rel >> 14, w = rel & 16383;
        int row = w >> 8, col = w & 255;
        v = (row < 48) ? xpw[layer * 12288 + row * 256 + col] : 0.f;
    } else {
        v = ow[idx - 589824];
    }
    split_store(v, g_whi, g_wlo, idx);
}

// ---------------- conv weight transpose ----------------
__global__ void k_cwprep(const float* __restrict__ cw) {
    int idx = blockIdx.x * 256 + threadIdx.x;
    if (idx >= 4 * 27 * 256) return;
    int layer = idx / 6912, rem = idx % 6912;
    int j = rem >> 8, c = rem & 255;
    g_cw[idx] = cw[layer * 6912 + c * 27 + j];
}

// ---------------- all-layer A prep ----------------
__global__ void k_prepA_all(const float* __restrict__ alog) {
    int layer = blockIdx.x, c = threadIdx.x;
    __shared__ int ok;
    if (c == 0) ok = 1;
    __syncthreads();
    bool good = true;
    #pragma unroll
    for (int n = 0; n < DSZ; n++) {
        float a = -expf(alog[(layer * 256 + c) * DSZ + n]);
        g_A[(layer * 256 + c) * DSZ + n] = a;
        if (fabsf(a + (float)(n + 1)) > 1e-3f) good = false;
    }
    if (!good) atomicAnd(&ok, 0);
    __syncthreads();
    if (c == 0) g_fastA[layer] = ok;
}

// ---------------- initial transpose ----------------
__global__ void k_init_tr(const float* __restrict__ x) {
    __shared__ float tile[32][33];
    int b = blockIdx.z >> 4, d = blockIdx.z & 15;
    int hw0 = blockIdx.x * 32, c0 = blockIdx.y * 32;
    int tx = threadIdx.x, ty = threadIdx.y;
    tile[ty][tx] = x[((size_t)(b*CC + c0 + ty) * 16 + d) * 256 + hw0 + tx];
    __syncthreads();
    g_t[((size_t)b*LL + (size_t)(hw0 + ty) * 16 + d) * CC + c0 + tx] = tile[tx][ty];
}

// ---------------- LN1 (warp per row) + bf16 split ----------------
__global__ __launch_bounds__(256)
void k_ln1(const float* __restrict__ g, const float* __restrict__ bvec) {
    int warp = threadIdx.x >> 5, lane = threadIdx.x & 31;
    int p = blockIdx.x * 8 + warp;
    const float4* row = (const float4*)(g_t + (size_t)p * CC);
    float4 v0 = row[lane * 2], v1 = row[lane * 2 + 1];
    float s  = v0.x + v0.y + v0.z + v0.w + v1.x + v1.y + v1.z + v1.w;
    float s2 = v0.x*v0.x + v0.y*v0.y + v0.z*v0.z + v0.w*v0.w
             + v1.x*v1.x + v1.y*v1.y + v1.z*v1.z + v1.w*v1.w;
    warpRed2(s, s2);
    float m  = s * (1.f / CC);
    float rs = rsqrtf(s2 * (1.f / CC) - m * m + 1e-5f);
    float4 gg0 = ((const float4*)g)[lane * 2],    gg1 = ((const float4*)g)[lane * 2 + 1];
    float4 bb0 = ((const float4*)bvec)[lane * 2], bb1 = ((const float4*)bvec)[lane * 2 + 1];
    float o[8];
    o[0] = (v0.x - m) * rs * gg0.x + bb0.x;  o[1] = (v0.y - m) * rs * gg0.y + bb0.y;
    o[2] = (v0.z - m) * rs * gg0.z + bb0.z;  o[3] = (v0.w - m) * rs * gg0.w + bb0.w;
    o[4] = (v1.x - m) * rs * gg1.x + bb1.x;  o[5] = (v1.y - m) * rs * gg1.y + bb1.y;
    o[6] = (v1.z - m) * rs * gg1.z + bb1.z;  o[7] = (v1.w - m) * rs * gg1.w + bb1.w;
    split8_store(o, g_ahi, g_alo, (size_t)p * CC, lane);
}

// ---------------- pipelined ldmatrix bf16x3 GEMM (pristine) ----------------
template<int NT>
__global__ __launch_bounds__(256, 3)
void k_mgemm(const uint32_t* __restrict__ Ahi, const uint32_t* __restrict__ Alo,
             const uint32_t* __restrict__ Bhi, const uint32_t* __restrict__ Blo,
             float* __restrict__ C, int ldc, int Nact, int mode) {
    constexpr int RB = 80;
    constexpr int AL_OFF = 128 * RB;
    constexpr int BH_OFF = 2 * 128 * RB;
    constexpr int BL_OFF = BH_OFF + NT * RB;
    constexpr int STAGE  = BH_OFF + 2 * NT * RB;
    constexpr int NTILES = NT / 16;
    constexpr int NPAIR  = NTILES / 2;

    extern __shared__ __align__(16) char smem[];
    uint32_t sbase = smem_u32(smem);
    int tid = threadIdx.x, wid = tid >> 5, lane = tid & 31;
    int g2 = lane >> 2, t4 = lane & 3;
    int row0 = blockIdx.y * 128, col0 = blockIdx.x * NT;
    int m0 = (wid >> 1) * 32, n0 = (wid & 1) * (NT / 2);
    uint32_t lmo = (uint32_t)(((lane & 7) + ((lane >> 3) & 1) * 8) * RB + (lane >> 4) * 16);

    float acc[2][NTILES][4];
    #pragma unroll
    for (int mt = 0; mt < 2; mt++)
        #pragma unroll
        for (int nt = 0; nt < NTILES; nt++)
            #pragma unroll
            for (int j = 0; j < 4; j++) acc[mt][nt][j] = 0.f;

    int lr = tid >> 2, lc4 = (tid & 3) * 4;

    auto load_chunk = [&](int kc, int stg) {
        uint32_t sb = sbase + stg * STAGE;
        int kw = kc * 16;
        #pragma unroll
        for (int i = 0; i < 2; i++) {
            int r = lr + i * 64;
            size_t gi = (size_t)(row0 + r) * 128 + kw + lc4;
            uint32_t so = (uint32_t)(r * RB + lc4 * 4);
            cpa16(sb + so,          Ahi + gi);
            cpa16(sb + AL_OFF + so, Alo + gi);
        }
        #pragma unroll
        for (int i = 0; i < NT / 64; i++) {
            int r = lr + i * 64;
            size_t gi = (size_t)(col0 + r) * 128 + kw + lc4;
            uint32_t so = (uint32_t)(r * RB + lc4 * 4);
            cpa16(sb + BH_OFF + so, Bhi + gi);
            cpa16(sb + BL_OFF + so, Blo + gi);
        }
    };

    load_chunk(0, 0); CPA_COMMIT();
    load_chunk(1, 1); CPA_COMMIT();

    #pragma unroll 1
    for (int kc = 0; kc < 8; kc++) {
        if (kc < 7) { CPA_WAIT(1); } else { CPA_WAIT(0); }
        __syncthreads();
        uint32_t sb = sbase + (kc & 1) * STAGE;
        uint32_t aH = sb + m0 * RB + lmo;
        uint32_t aL = aH + AL_OFF;
        uint32_t bH = sb + BH_OFF + n0 * RB + lmo;
        uint32_t bL = bH + NT * RB;
        #pragma unroll
        for (int step = 0; step < 2; step++) {
            uint32_t ko = step * 32;
            uint32_t ah[2][4], al[2][4];
            #pragma unroll
            for (int mt = 0; mt < 2; mt++) {
                ldsm4(ah[mt], aH + mt * 16 * RB + ko);
                ldsm4(al[mt], aL + mt * 16 * RB + ko);
            }
            #pragma unroll
            for (int p = 0; p < NPAIR; p++) {
                uint32_t bh[4], bl[4];
                ldsm4(bh, bH + p * 16 * RB + ko);
                ldsm4(bl, bL + p * 16 * RB + ko);
                #pragma unroll
                for (int sub = 0; sub < 2; sub++) {
                    uint32_t b0h = bh[sub], b1h = bh[2 + sub];
                    uint32_t b0l = bl[sub], b1l = bl[2 + sub];
                    #pragma unroll
                    for (int mt = 0; mt < 2; mt++) {
                        mma16816(acc[mt][2 * p + sub], ah[mt], b0h, b1h);
                        mma16816(acc[mt][2 * p + sub], ah[mt], b0l, b1l);
                        mma16816(acc[mt][2 * p + sub], al[mt], b0h, b1h);
                    }
                }
            }
        }
        __syncthreads();
        if (kc + 2 < 8) { load_chunk(kc + 2, kc & 1); CPA_COMMIT(); }
    }

    #pragma unroll
    for (int mt = 0; mt < 2; mt++) {
        int rA = row0 + m0 + mt * 16 + g2;
        int rB = rA + 8;
        #pragma unroll
        for (int nt = 0; nt < NTILES; nt++) {
            int cA = col0 + n0 + nt * 8 + 2 * t4;
            #pragma unroll
            for (int j = 0; j < 2; j++) {
                int c = cA + j;
                if (c < Nact) {
                    float v0 = acc[mt][nt][j];
                    float v1 = acc[mt][nt][2 + j];
                    if (mode == 1) {
                        v0 += C[(size_t)rA * ldc + c];
                        v1 += C[(size_t)rB * ldc + c];
                    }
                    C[(size_t)rA * ldc + c] = v0;
                    C[(size_t)rB * ldc + c] = v1;
                }
            }
        }
    }
}

// ---------------- depthwise 3x3x3 conv + SiLU + flip ----------------
__global__ __launch_bounds__(256)
void k_conv(int layer, const float* __restrict__ convb, int ori) {
    int bidx = blockIdx.x;
    int b = bidx >> 8, h = (bidx >> 4) & 15, w = bidx & 15;
    int c = threadIdx.x;
    const float* wt = g_cw + layer * 6912;
    float wr[27];
    #pragma unroll
    for (int j = 0; j < 27; j++) wr[j] = wt[j * 256 + c];
    float bias = convb[c];
    float acc[16];
    #pragma unroll
    for (int d = 0; d < 16; d++) acc[d] = bias;

    #pragma unroll
    for (int s1 = 0; s1 < 3; s1++) {
        int hh = h + s1 - 1; if (hh < 0 || hh > 15) continue;
        #pragma unroll
        for (int s2 = 0; s2 < 3; s2++) {
            int ww = w + s2 - 1; if (ww < 0 || ww > 15) continue;
            size_t cb = ((size_t)(b * LL + (hh * 16 + ww) * 16)) * 512 + c;
            float col[16];
            #pragma unroll
            for (int dd = 0; dd < 16; dd++) col[dd] = g_xz[cb + (size_t)dd * 512];
            float w0 = wr[s1 * 9 + s2 * 3 + 0];
            float w1 = wr[s1 * 9 + s2 * 3 + 1];
            float w2 = wr[s1 * 9 + s2 * 3 + 2];
            #pragma unroll
            for (int d = 0; d < 16; d++) {
                float a = w1 * col[d];
                if (d > 0)  a += w0 * col[d - 1];
                if (d < 15) a += w2 * col[d + 1];
                acc[d] += a;
            }
        }
    }
    int fh = (ori & 1) ? 15 - h : h;
    int fw = (ori & 2) ? 15 - w : w;
    #pragma unroll
    for (int d = 0; d < 16; d++) {
        float sv = acc[d] / (1.f + expf(-acc[d]));
        int fd = (ori & 4) ? 15 - d : d;
        size_t oi = ((size_t)b * LL + (fh * 16 + fw) * 16 + fd) * CC + c;
        split_store(sv, g_ahi, g_alo, oi);
    }
}

// ---------------- FUSED scan + gate: phases A+B+C+D, 128 blocks x 256 thr ----------------
// Block (ch, b) holds all 256 channels of positions [ch*CLN, ch*CLN+CLN).
// Phase C parks y in smem (dxS slab, dead after use); phase D does warp-per-row
// LN + SiLU gate straight from smem (bitwise identical to old k_gate), writing
// splits at unflipped position p = flip(q). No g_y global traffic, no new barrier.
__global__ __launch_bounds__(256)
void k_scanF(int layer, const float* __restrict__ dtw_, const float* __restrict__ dtb_,
             const float* __restrict__ Dv, int ori,
             const float* __restrict__ og, const float* __restrict__ ob) {
    extern __shared__ float sm[];
    float* rvS  = sm;                    // [CLN*256] rv (fast) or sp (generic)
    float* dxS  = sm + CLN * 256;        // [CLN*256] dtx, then y
    float* xvS  = sm + 2 * CLN * 256;    // [CLN*256] xv
    float* Bsm  = sm + 3 * CLN * 256;    // [CLN*16]
    float* Csm  = Bsm + CLN * 16;        // [CLN*16]
    float* dtsm = Csm + CLN * 16;        // [CLN*16]

    int tid = threadIdx.x;
    int c = tid;
    int ch = blockIdx.x, b = blockIdx.z;
    int fast = g_fastA[layer];

    for (int i = tid; i < CLN * 48; i += 256) {
        int t = i / 48, j = i % 48;
        float v = g_dbl[((size_t)b * LL + ch * CLN + t) * 48 + j];
        if (j < 16) dtsm[t * 16 + j] = v;
        else if (j < 32) Bsm[t * 16 + (j - 16)] = v;
        else Csm[t * 16 + (j - 32)] = v;
    }
    __syncthreads();

    float dw[DSZ];
    #pragma unroll
    for (int j = 0; j < DSZ; j++) dw[j] = dtw_[c * DSZ + j];
    float db = dtb_[c];

    // ---- phase A ----
    float h[DSZ], P[DSZ];
    #pragma unroll
    for (int n = 0; n < DSZ; n++) { h[n] = 0.f; P[n] = 1.f; }
    size_t base = ((size_t)b * LL + ch * CLN) * CC + c;
    if (fast) {
        #pragma unroll 4
        for (int t = 0; t < CLN; t++) {
            size_t gi = base + (size_t)t * CC;
            float xv = __bfloat162float(g_ahi[gi]) + __bfloat162float(g_alo[gi]);
            float traw = db;
            #pragma unroll
            for (int j = 0; j < DSZ; j++) traw += dw[j] * dtsm[t * 16 + j];
            float sp = fmaxf(traw, 0.f) + log1pf(expf(-fabsf(traw)));
            float rv = expf(-sp);
            float dtx = sp * xv;
            rvS[t * 256 + tid] = rv;
            dxS[t * 256 + tid] = dtx;
            xvS[t * 256 + tid] = xv;
            float rp[16];
            rpow16(rv, rp);
            #pragma unroll
            for (int n = 0; n < DSZ; n++) {
                h[n] = rp[n] * h[n] + dtx * Bsm[t * 16 + n];
                P[n] *= rp[n];
            }
        }
    } else {
        #pragma unroll 2
        for (int t = 0; t < CLN; t++) {
            size_t gi = base + (size_t)t * CC;
            float xv = __bfloat162float(g_ahi[gi]) + __bfloat162float(g_alo[gi]);
            float traw = db;
            #pragma unroll
            for (int j = 0; j < DSZ; j++) traw += dw[j] * dtsm[t * 16 + j];
            float sp = fmaxf(traw, 0.f) + log1pf(expf(-fabsf(traw)));
            float dtx = sp * xv;
            rvS[t * 256 + tid] = sp;
            dxS[t * 256 + tid] = dtx;
            xvS[t * 256 + tid] = xv;
            #pragma unroll
            for (int n = 0; n < DSZ; n++) {
                float dA = __expf(sp * g_A[((layer * 256) + c) * DSZ + n]);
                h[n] = dA * h[n] + dtx * Bsm[t * 16 + n];
                P[n] *= dA;
            }
        }
    }
    size_t off = (((size_t)(b * CC + c)) * NCH + ch) * DSZ;
    #pragma unroll
    for (int n = 0; n < DSZ; n++) { g_hend[off + n] = h[n]; g_P[off + n] = P[n]; }

    gridbar(0);

    // ---- phase B: sequential chunk combine ----
    {
        int rank = (blockIdx.z * NCH + blockIdx.x) * 256 + tid;
        if (rank < BB * CC * DSZ) {
            int n = rank & 15, bc = rank >> 4;
            float H = 0.f;
            size_t bb2 = (size_t)bc * NCH * DSZ + n;
            for (int k0 = 0; k0 < NCH; k0 += 8) {
                float Pv[8], Ev[8];
                #pragma unroll
                for (int q = 0; q < 8; q++) {
                    size_t o = bb2 + (size_t)(k0 + q) * DSZ;
                    Pv[q] = g_P[o];
                    Ev[q] = g_hend[o];
                }
                #pragma unroll
                for (int q = 0; q < 8; q++) {
                    g_hst[bb2 + (size_t)(k0 + q) * DSZ] = H;
                    H = Pv[q] * H + Ev[q];
                }
            }
        }
    }

    gridbar(1);

    // ---- phase C: replay, y -> smem (dxS slab) ----
    #pragma unroll
    for (int n = 0; n < DSZ; n++) h[n] = g_hst[off + n];
    float Dc = Dv[c];
    if (fast) {
        #pragma unroll 4
        for (int t = 0; t < CLN; t++) {
            float rv  = rvS[t * 256 + tid];
            float dtx = dxS[t * 256 + tid];
            float xv  = xvS[t * 256 + tid];
            float rp[16];
            rpow16(rv, rp);
            float y = 0.f;
            #pragma unroll
            for (int n = 0; n < DSZ; n++) {
                h[n] = rp[n] * h[n] + dtx * Bsm[t * 16 + n];
                y += h[n] * Csm[t * 16 + n];
            }
            dxS[t * 256 + tid] = y + Dc * xv;
        }
    } else {
        #pragma unroll 2
        for (int t = 0; t < CLN; t++) {
            float sp  = rvS[t * 256 + tid];
            float dtx = dxS[t * 256 + tid];
            float xv  = xvS[t * 256 + tid];
            float y = 0.f;
            #pragma unroll
            for (int n = 0; n < DSZ; n++) {
                float dA = __expf(sp * g_A[((layer * 256) + c) * DSZ + n]);
                h[n] = dA * h[n] + dtx * Bsm[t * 16 + n];
                y += h[n] * Csm[t * 16 + n];
            }
            dxS[t * 256 + tid] = y + Dc * xv;
        }
    }
    __syncthreads();

    // ---- phase D: LN + SiLU gate from smem, write splits at p = flip(q) ----
    {
        int warp = tid >> 5, lane = tid & 31;
        #pragma unroll
        for (int rr = 0; rr < 8; rr++) {
            int t = warp * 8 + rr;
            int q = ch * CLN + t;                 // flipped storage position
            int hh = q >> 8, ww = (q >> 4) & 15, dd = q & 15;
            if (ori & 1) hh = 15 - hh;
            if (ori & 2) ww = 15 - ww;
            if (ori & 4) dd = 15 - dd;
            int p = (b << 12) | (hh << 8) | (ww << 4) | dd;   // output position
            const float4* yr = (const float4*)(dxS + t * 256);
            float4 v0 = yr[lane * 2], v1 = yr[lane * 2 + 1];
            float s  = v0.x + v0.y + v0.z + v0.w + v1.x + v1.y + v1.z + v1.w;
            float s2 = v0.x*v0.x + v0.y*v0.y + v0.z*v0.z + v0.w*v0.w
                     + v1.x*v1.x + v1.y*v1.y + v1.z*v1.z + v1.w*v1.w;
            warpRed2(s, s2);
            float m  = s * (1.f / CC);
            float rs = rsqrtf(s2 * (1.f / CC) - m * m + 1e-5f);
            const float4* zr = (const float4*)(g_xz + (size_t)p * 512 + 256);
            float4 z0 = zr[lane * 2], z1 = zr[lane * 2 + 1];
            float4 gg0 = ((const float4*)og)[lane * 2], gg1 = ((const float4*)og)[lane * 2 + 1];
            float4 bb0 = ((const float4*)ob)[lane * 2], bb1 = ((const float4*)ob)[lane * 2 + 1];
            float vv[8] = {v0.x, v0.y, v0.z, v0.w, v1.x, v1.y, v1.z, v1.w};
            float zz[8] = {z0.x, z0.y, z0.z, z0.w, z1.x, z1.y, z1.z, z1.w};
            float ga[8] = {gg0.x, gg0.y, gg0.z, gg0.w, gg1.x, gg1.y, gg1.z, gg1.w};
            float ba[8] = {bb0.x, bb0.y, bb0.z, bb0.w, bb1.x, bb1.y, bb1.z, bb1.w};
            float o[8];
            #pragma unroll
            for (int k = 0; k < 8; k++) {
                float sz = zz[k] / (1.f + expf(-zz[k]));
                o[k] = ((vv[k] - m) * rs * ga[k] + ba[k]) * sz;
            }
            split8_store(o, g_ahi, g_alo, (size_t)p * CC, lane);
        }
    }
}

// ---------------- post-LN stats ----------------
__global__ __launch_bounds__(256)
void k_stats() {
    int warp = threadIdx.x >> 5, lane = threadIdx.x & 31;
    int p = blockIdx.x * 8 + warp;
    const float4* row = (const float4*)(g_t + (size_t)p * CC);
    float4 v0 = row[lane * 2], v1 = row[lane * 2 + 1];
    float s  = v0.x + v0.y + v0.z + v0.w + v1.x + v1.y + v1.z + v1.w;
    float s2 = v0.x*v0.x + v0.y*v0.y + v0.z*v0.z + v0.w*v0.w
             + v1.x*v1.x + v1.y*v1.y + v1.z*v1.z + v1.w*v1.w;
    warpRed2(s, s2);
    if (lane == 0) {
        float m = s * (1.f / CC);
        g_rowm[p] = m;
        g_rowrs[p] = rsqrtf(s2 * (1.f / CC) - m * m + 1e-5f);
    }
}

// ---------------- final transpose + post-LN apply ----------------
__global__ void k_final_tr(float* __restrict__ out,
                           const float* __restrict__ pg, const float* __restrict__ pb) {
    __shared__ float tile[32][33];
    int b = blockIdx.z >> 4, d = blockIdx.z & 15;
    int hw0 = blockIdx.x * 32, c0 = blockIdx.y * 32;
    int tx = threadIdx.x, ty = threadIdx.y;
    int p = b * LL + (hw0 + ty) * 16 + d;
    int c = c0 + tx;
    float v = g_t[(size_t)p * CC + c];
    tile[ty][tx] = (v - g_rowm[p]) * g_rowrs[p] * pg[c] + pb[c];
    __syncthreads();
    out[((size_t)(b * CC + c0 + ty) * 16 + d) * 256 + hw0 + tx] = tile[tx][ty];
}

// ---------------- host ----------------
extern "C" void kernel_launch(void* const* d_in, const int* in_sizes, int n_in,
                              void* d_out, int out_size) {
    const float* x       = (const float*)d_in[0];
    const float* in_w    = (const float*)d_in[1];
    const float* conv_w  = (const float*)d_in[2];
    const float* conv_b  = (const float*)d_in[3];
    const float* xproj_w = (const float*)d_in[4];
    const float* dt_w    = (const float*)d_in[5];
    const float* dt_b    = (const float*)d_in[6];
    const float* A_log   = (const float*)d_in[7];
    const float* D_skip  = (const float*)d_in[8];
    const float* on_g    = (const float*)d_in[9];
    const float* on_b    = (const float*)d_in[10];
    const float* out_w   = (const float*)d_in[11];
    const float* ln1_g   = (const float*)d_in[12];
    const float* ln1_b   = (const float*)d_in[13];
    const float* post_g  = (const float*)d_in[14];
    const float* post_b  = (const float*)d_in[15];
    float* out = (float*)d_out;

    void *p_t, *p_xz, *p_dbl, *p_ahi, *p_alo, *p_whi, *p_wlo;
    cudaGetSymbolAddress(&p_t,   g_t);
    cudaGetSymbolAddress(&p_xz,  g_xz);
    cudaGetSymbolAddress(&p_dbl, g_dbl);
    cudaGetSymbolAddress(&p_ahi, g_ahi);
    cudaGetSymbolAddress(&p_alo, g_alo);
    cudaGetSymbolAddress(&p_whi, g_whi);
    cudaGetSymbolAddress(&p_wlo, g_wlo);
    const uint32_t* whi = (const uint32_t*)p_whi;
    const uint32_t* wlo = (const uint32_t*)p_wlo;

    const int SM64  = 2 * (2 * 128 * 80 + 2 * 64 * 80);        // 61440 B
    const int SMEMF = (3 * CLN * 256 + 3 * CLN * 16) * 4;      // 208896 B
    static int attr_done = 0;
    if (!attr_done) {
        cudaFuncSetAttribute(k_mgemm<64>, cudaFuncAttributeMaxDynamicSharedMemorySize, SM64);
        cudaFuncSetAttribute(k_scanF,     cudaFuncAttributeMaxDynamicSharedMemorySize, SMEMF);
        attr_done = 1;
    }

    k_wsplit_all<<<(WTOT + 255) / 256, 256>>>(in_w, xproj_w, out_w);
    k_cwprep<<<108, 256>>>(conv_w);
    k_prepA_all<<<4, 256>>>(A_log);
    k_init_tr<<<dim3(8, 8, 32), dim3(32, 32)>>>(x);

    for (int i = 0; i < 4; i++) {
        int ori = i;  // i % 8
        k_ln1<<<1024, 256>>>(ln1_g + i * 256, ln1_b + i * 256);
        // in-proj: (8192 x 512)
        k_mgemm<64><<<dim3(8, 64), 256, SM64>>>(
            (const uint32_t*)p_ahi, (const uint32_t*)p_alo,
            whi + WOFF_IN(i) / 2, wlo + WOFF_IN(i) / 2,
            (float*)p_xz, 512, 512, 0);
        k_conv<<<BB * 256, 256>>>(i, conv_b + i * 256, ori);
        // xproj: (8192 x 48)
        k_mgemm<64><<<dim3(1, 64), 256, SM64>>>(
            (const uint32_t*)p_ahi, (const uint32_t*)p_alo,
            whi + WOFF_XP(i) / 2, wlo + WOFF_XP(i) / 2,
            (float*)p_dbl, 48, 48, 0);
        // fused scan (A+B+C) + gate (D, smem-resident)
        k_scanF<<<dim3(NCH, 1, BB), 256, SMEMF>>>(i, dt_w + (size_t)i * 4096,
                                                  dt_b + i * 256, D_skip + i * 256,
                                                  ori, on_g + i * 256, on_b + i * 256);
        // out-proj + residual into t
        k_mgemm<64><<<dim3(4, 64), 256, SM64>>>(
            (const uint32_t*)p_ahi, (const uint32_t*)p_alo,
            whi + WOFF_OUT(i) / 2, wlo + WOFF_OUT(i) / 2,
            (float*)p_t, 256, 256, 1);
    }

    k_stats<<<1024, 256>>>();
    k_final_tr<<<dim3(8, 8, 32), dim3(32, 32)>>>(out, post_g, post_b);
}

// round 15
// speedup vs baseline: 1.0717x; 1.0140x over previous
#include <cuda_runtime.h>
#include <cuda_bf16.h>
#include <math.h>
#include <stdint.h>

#define BB   2
#define CC   256
#define LL   4096
#define DSZ  16
#define NCH  64
#define CLN  64          // LL / NCH
#define NPOS (BB*LL)     // 8192
#define NBLK 128         // fused-scan grid size (1 block/SM, co-resident)

// weight-split buffer layout (bf16 elements)
#define WOFF_IN(i)   ((i) * 131072)
#define WOFF_XP(i)   (524288 + (i) * 16384)
#define WOFF_OUT(i)  (589824 + (i) * 65536)
#define WTOT 851968

// ---------------- scratch ----------------
__device__ float g_t[NPOS*CC];
__device__ float g_xz[NPOS*2*CC];
__device__ float g_dbl[NPOS*48];
__device__ float g_rowm[NPOS];
__device__ float g_rowrs[NPOS];
__device__ float g_A[4*CC*DSZ];
__device__ int   g_fastA[4];
__device__ float g_cw[4*27*CC];
__device__ float g_P[BB*CC*NCH*DSZ];
__device__ float g_hend[BB*CC*NCH*DSZ];
__device__ float g_hst[BB*CC*NCH*DSZ];
__device__ unsigned g_bar[2];            // monotonic grid-barrier tickets
__device__ __nv_bfloat16 g_ahi[NPOS*CC];
__device__ __nv_bfloat16 g_alo[NPOS*CC];
__device__ __nv_bfloat16 g_whi[WTOT];
__device__ __nv_bfloat16 g_wlo[WTOT];

// ---------------- helpers ----------------
__device__ __forceinline__ uint32_t smem_u32(const void* p) {
    uint32_t a;
    asm("{ .reg .u64 t; cvta.to.shared.u64 t, %1; cvt.u32.u64 %0, t; }" : "=r"(a) : "l"(p));
    return a;
}
__device__ __forceinline__ void warpRed2(float& s, float& s2) {
    #pragma unroll
    for (int o = 16; o; o >>= 1) {
        s  += __shfl_xor_sync(0xffffffffu, s,  o);
        s2 += __shfl_xor_sync(0xffffffffu, s2, o);
    }
}
__device__ __forceinline__ uint32_t packbf2(float a, float b) {
    __nv_bfloat162 t = __floats2bfloat162_rn(a, b);
    return *(uint32_t*)&t;
}
__device__ __forceinline__ void split8_store(const float o[8],
                                             __nv_bfloat16* hiB, __nv_bfloat16* loB,
                                             size_t rowoff, int lane) {
    float hf[8], lf[8];
    #pragma unroll
    for (int k = 0; k < 8; k++) {
        __nv_bfloat16 h = __float2bfloat16(o[k]);
        hf[k] = __bfloat162float(h);
        lf[k] = o[k] - hf[k];
    }
    uint4 uh, ul;
    uh.x = packbf2(hf[0], hf[1]); uh.y = packbf2(hf[2], hf[3]);
    uh.z = packbf2(hf[4], hf[5]); uh.w = packbf2(hf[6], hf[7]);
    ul.x = packbf2(lf[0], lf[1]); ul.y = packbf2(lf[2], lf[3]);
    ul.z = packbf2(lf[4], lf[5]); ul.w = packbf2(lf[6], lf[7]);
    ((uint4*)(hiB + rowoff))[lane] = uh;
    ((uint4*)(loB + rowoff))[lane] = ul;
}
__device__ __forceinline__ void split_store(float v, __nv_bfloat16* hi, __nv_bfloat16* lo, size_t i) {
    __nv_bfloat16 h = __float2bfloat16(v);
    hi[i] = h;
    lo[i] = __float2bfloat16(v - __bfloat162float(h));
}
__device__ __forceinline__ void mma16816(float c[4], const uint32_t a[4],
                                         uint32_t b0, uint32_t b1) {
    asm volatile(
        "mma.sync.aligned.m16n8k16.row.col.f32.bf16.bf16.f32 "
        "{%0,%1,%2,%3}, {%4,%5,%6,%7}, {%8,%9}, {%0,%1,%2,%3};"
        : "+f"(c[0]), "+f"(c[1]), "+f"(c[2]), "+f"(c[3])
        : "r"(a[0]), "r"(a[1]), "r"(a[2]), "r"(a[3]), "r"(b0), "r"(b1));
}
__device__ __forceinline__ void ldsm4(uint32_t r[4], uint32_t addr) {
    asm volatile("ldmatrix.sync.aligned.m8n8.x4.shared.b16 {%0,%1,%2,%3}, [%4];"
        : "=r"(r[0]), "=r"(r[1]), "=r"(r[2]), "=r"(r[3]) : "r"(addr));
}
__device__ __forceinline__ void cpa16(uint32_t saddr, const void* g) {
    asm volatile("cp.async.cg.shared.global [%0], [%1], 16;" :: "r"(saddr), "l"(g));
}
#define CPA_COMMIT() asm volatile("cp.async.commit_group;" ::: "memory")
#define CPA_WAIT(N)  asm volatile("cp.async.wait_group %0;" :: "n"(N) : "memory")

// r^1..r^16 via log-depth tree
__device__ __forceinline__ void rpow16(float rv, float rp[16]) {
    float r2 = rv * rv, r4 = r2 * r2, r8 = r4 * r4;
    rp[0] = rv;        rp[1] = r2;        rp[2] = r2 * rv;   rp[3] = r4;
    rp[4] = r4 * rv;   rp[5] = r4 * r2;   rp[6] = r4 * rp[2]; rp[7] = r8;
    rp[8] = r8 * rv;   rp[9] = r8 * r2;   rp[10] = r8 * rp[2]; rp[11] = r8 * r4;
    rp[12] = r8 * rp[4]; rp[13] = r8 * rp[5]; rp[14] = r8 * rp[6]; rp[15] = r8 * r8;
}

// monotonic-ticket grid barrier (all NBLK blocks co-resident; graph-replay safe)
__device__ __forceinline__ void gridbar(int slot) {
    __syncthreads();
    if (threadIdx.x == 0) {
        __threadfence();
        unsigned ticket = atomicAdd(&g_bar[slot], 1u) + 1u;
        unsigned target = ((ticket - 1u) / NBLK + 1u) * NBLK;
        while ((int)(*(volatile unsigned*)&g_bar[slot] - target) < 0) { }
        __threadfence();
    }
    __syncthreads();
}

// ---------------- all-layer weight split ----------------
__global__ void k_wsplit_all(const float* __restrict__ inw,
                             const float* __restrict__ xpw,
                             const float* __restrict__ ow) {
    int idx = blockIdx.x * 256 + threadIdx.x;
    if (idx >= WTOT) return;
    float v;
    if (idx < 524288) {
        v = inw[idx];
    } else if (idx < 589824) {
        int rel = idx - 524288;
        int layer = rel >> 14, w = rel & 16383;
        int row = w >> 8, col = w & 255;
        v = (row < 48) ? xpw[layer * 12288 + row * 256 + col] : 0.f;
    } else {
        v = ow[idx - 589824];
    }
    split_store(v, g_whi, g_wlo, idx);
}

// ---------------- conv weight transpose ----------------
__global__ void k_cwprep(const float* __restrict__ cw) {
    int idx = blockIdx.x * 256 + threadIdx.x;
    if (idx >= 4 * 27 * 256) return;
    int layer = idx / 6912, rem = idx % 6912;
    int j = rem >> 8, c = rem & 255;
    g_cw[idx] = cw[layer * 6912 + c * 27 + j];
}

// ---------------- all-layer A prep ----------------
__global__ void k_prepA_all(const float* __restrict__ alog) {
    int layer = blockIdx.x, c = threadIdx.x;
    __shared__ int ok;
    if (c == 0) ok = 1;
    __syncthreads();
    bool good = true;
    #pragma unroll
    for (int n = 0; n < DSZ; n++) {
        float a = -expf(alog[(layer * 256 + c) * DSZ + n]);
        g_A[(layer * 256 + c) * DSZ + n] = a;
        if (fabsf(a + (float)(n + 1)) > 1e-3f) good = false;
    }
    if (!good) atomicAnd(&ok, 0);
    __syncthreads();
    if (c == 0) g_fastA[layer] = ok;
}

// ---------------- initial transpose ----------------
__global__ void k_init_tr(const float* __restrict__ x) {
    __shared__ float tile[32][33];
    int b = blockIdx.z >> 4, d = blockIdx.z & 15;
    int hw0 = blockIdx.x * 32, c0 = blockIdx.y * 32;
    int tx = threadIdx.x, ty = threadIdx.y;
    tile[ty][tx] = x[((size_t)(b*CC + c0 + ty) * 16 + d) * 256 + hw0 + tx];
    __syncthreads();
    g_t[((size_t)b*LL + (size_t)(hw0 + ty) * 16 + d) * CC + c0 + tx] = tile[tx][ty];
}

// ---------------- LN1 (warp per row) + bf16 split ----------------
__global__ __launch_bounds__(256)
void k_ln1(const float* __restrict__ g, const float* __restrict__ bvec) {
    int warp = threadIdx.x >> 5, lane = threadIdx.x & 31;
    int p = blockIdx.x * 8 + warp;
    const float4* row = (const float4*)(g_t + (size_t)p * CC);
    float4 v0 = row[lane * 2], v1 = row[lane * 2 + 1];
    float s  = v0.x + v0.y + v0.z + v0.w + v1.x + v1.y + v1.z + v1.w;
    float s2 = v0.x*v0.x + v0.y*v0.y + v0.z*v0.z + v0.w*v0.w
             + v1.x*v1.x + v1.y*v1.y + v1.z*v1.z + v1.w*v1.w;
    warpRed2(s, s2);
    float m  = s * (1.f / CC);
    float rs = rsqrtf(s2 * (1.f / CC) - m * m + 1e-5f);
    float4 gg0 = ((const float4*)g)[lane * 2],    gg1 = ((const float4*)g)[lane * 2 + 1];
    float4 bb0 = ((const float4*)bvec)[lane * 2], bb1 = ((const float4*)bvec)[lane * 2 + 1];
    float o[8];
    o[0] = (v0.x - m) * rs * gg0.x + bb0.x;  o[1] = (v0.y - m) * rs * gg0.y + bb0.y;
    o[2] = (v0.z - m) * rs * gg0.z + bb0.z;  o[3] = (v0.w - m) * rs * gg0.w + bb0.w;
    o[4] = (v1.x - m) * rs * gg1.x + bb1.x;  o[5] = (v1.y - m) * rs * gg1.y + bb1.y;
    o[6] = (v1.z - m) * rs * gg1.z + bb1.z;  o[7] = (v1.w - m) * rs * gg1.w + bb1.w;
    split8_store(o, g_ahi, g_alo, (size_t)p * CC, lane);
}

// ---------------- pipelined ldmatrix bf16x3 GEMM, STG-stage ----------------
// STG=2: classic double-buffer (2 syncs/chunk). STG=3: single-sync/chunk
// (load k+2 right after top sync; it overwrites stage (k+2)%3 which held k-1,
// proven consumed by that same sync).
template<int NT, int STG>
__global__ __launch_bounds__(256, 2)
void k_mgemm(const uint32_t* __restrict__ Ahi, const uint32_t* __restrict__ Alo,
             const uint32_t* __restrict__ Bhi, const uint32_t* __restrict__ Blo,
             float* __restrict__ C, int ldc, int Nact, int mode) {
    constexpr int RB = 80;
    constexpr int AL_OFF = 128 * RB;
    constexpr int BH_OFF = 2 * 128 * RB;
    constexpr int BL_OFF = BH_OFF + NT * RB;
    constexpr int STAGE  = BH_OFF + 2 * NT * RB;
    constexpr int NTILES = NT / 16;
    constexpr int NPAIR  = NTILES / 2;

    extern __shared__ __align__(16) char smem[];
    uint32_t sbase = smem_u32(smem);
    int tid = threadIdx.x, wid = tid >> 5, lane = tid & 31;
    int g2 = lane >> 2, t4 = lane & 3;
    int row0 = blockIdx.y * 128, col0 = blockIdx.x * NT;
    int m0 = (wid >> 1) * 32, n0 = (wid & 1) * (NT / 2);
    uint32_t lmo = (uint32_t)(((lane & 7) + ((lane >> 3) & 1) * 8) * RB + (lane >> 4) * 16);

    float acc[2][NTILES][4];
    #pragma unroll
    for (int mt = 0; mt < 2; mt++)
        #pragma unroll
        for (int nt = 0; nt < NTILES; nt++)
            #pragma unroll
            for (int j = 0; j < 4; j++) acc[mt][nt][j] = 0.f;

    int lr = tid >> 2, lc4 = (tid & 3) * 4;

    auto load_chunk = [&](int kc, int stg) {
        uint32_t sb = sbase + stg * STAGE;
        int kw = kc * 16;
        #pragma unroll
        for (int i = 0; i < 2; i++) {
            int r = lr + i * 64;
            size_t gi = (size_t)(row0 + r) * 128 + kw + lc4;
            uint32_t so = (uint32_t)(r * RB + lc4 * 4);
            cpa16(sb + so,          Ahi + gi);
            cpa16(sb + AL_OFF + so, Alo + gi);
        }
        #pragma unroll
        for (int i = 0; i < NT / 64; i++) {
            int r = lr + i * 64;
            size_t gi = (size_t)(col0 + r) * 128 + kw + lc4;
            uint32_t so = (uint32_t)(r * RB + lc4 * 4);
            cpa16(sb + BH_OFF + so, Bhi + gi);
            cpa16(sb + BL_OFF + so, Blo + gi);
        }
    };

    auto compute_chunk = [&](int stg) {
        uint32_t sb = sbase + stg * STAGE;
        uint32_t aH = sb + m0 * RB + lmo;
        uint32_t aL = aH + AL_OFF;
        uint32_t bH = sb + BH_OFF + n0 * RB + lmo;
        uint32_t bL = bH + NT * RB;
        #pragma unroll
        for (int step = 0; step < 2; step++) {
            uint32_t ko = step * 32;
            uint32_t ah[2][4], al[2][4];
            #pragma unroll
            for (int mt = 0; mt < 2; mt++) {
                ldsm4(ah[mt], aH + mt * 16 * RB + ko);
                ldsm4(al[mt], aL + mt * 16 * RB + ko);
            }
            #pragma unroll
            for (int p = 0; p < NPAIR; p++) {
                uint32_t bh[4], bl[4];
                ldsm4(bh, bH + p * 16 * RB + ko);
                ldsm4(bl, bL + p * 16 * RB + ko);
                #pragma unroll
                for (int sub = 0; sub < 2; sub++) {
                    uint32_t b0h = bh[sub], b1h = bh[2 + sub];
                    uint32_t b0l = bl[sub], b1l = bl[2 + sub];
                    #pragma unroll
                    for (int mt = 0; mt < 2; mt++) {
                        mma16816(acc[mt][2 * p + sub], ah[mt], b0h, b1h);
                        mma16816(acc[mt][2 * p + sub], ah[mt], b0l, b1l);
                        mma16816(acc[mt][2 * p + sub], al[mt], b0h, b1h);
                    }
                }
            }
        }
    };

    load_chunk(0, 0); CPA_COMMIT();
    load_chunk(1, 1); CPA_COMMIT();

    if (STG == 3) {
        #pragma unroll 1
        for (int kc = 0; kc < 8; kc++) {
            if (kc < 7) { CPA_WAIT(1); } else { CPA_WAIT(0); }
            __syncthreads();
            if (kc + 2 < 8) { load_chunk(kc + 2, (kc + 2) % 3); CPA_COMMIT(); }
            compute_chunk(kc % 3);
        }
    } else {
        #pragma unroll 1
        for (int kc = 0; kc < 8; kc++) {
            if (kc < 7) { CPA_WAIT(1); } else { CPA_WAIT(0); }
            __syncthreads();
            compute_chunk(kc & 1);
            __syncthreads();
            if (kc + 2 < 8) { load_chunk(kc + 2, kc & 1); CPA_COMMIT(); }
        }
    }

    #pragma unroll
    for (int mt = 0; mt < 2; mt++) {
        int rA = row0 + m0 + mt * 16 + g2;
        int rB = rA + 8;
        #pragma unroll
        for (int nt = 0; nt < NTILES; nt++) {
            int cA = col0 + n0 + nt * 8 + 2 * t4;
            #pragma unroll
            for (int j = 0; j < 2; j++) {
                int c = cA + j;
                if (c < Nact) {
                    float v0 = acc[mt][nt][j];
                    float v1 = acc[mt][nt][2 + j];
                    if (mode == 1) {
                        v0 += C[(size_t)rA * ldc + c];
                        v1 += C[(size_t)rB * ldc + c];
                    }
                    C[(size_t)rA * ldc + c] = v0;
                    C[(size_t)rB * ldc + c] = v1;
                }
            }
        }
    }
}

// ---------------- depthwise 3x3x3 conv + SiLU + flip ----------------
__global__ __launch_bounds__(256)
void k_conv(int layer, const float* __restrict__ convb, int ori) {
    int bidx = blockIdx.x;
    int b = bidx >> 8, h = (bidx >> 4) & 15, w = bidx & 15;
    int c = threadIdx.x;
    const float* wt = g_cw + layer * 6912;
    float wr[27];
    #pragma unroll
    for (int j = 0; j < 27; j++) wr[j] = wt[j * 256 + c];
    float bias = convb[c];
    float acc[16];
    #pragma unroll
    for (int d = 0; d < 16; d++) acc[d] = bias;

    #pragma unroll
    for (int s1 = 0; s1 < 3; s1++) {
        int hh = h + s1 - 1; if (hh < 0 || hh > 15) continue;
        #pragma unroll
        for (int s2 = 0; s2 < 3; s2++) {
            int ww = w + s2 - 1; if (ww < 0 || ww > 15) continue;
            size_t cb = ((size_t)(b * LL + (hh * 16 + ww) * 16)) * 512 + c;
            float col[16];
            #pragma unroll
            for (int dd = 0; dd < 16; dd++) col[dd] = g_xz[cb + (size_t)dd * 512];
            float w0 = wr[s1 * 9 + s2 * 3 + 0];
            float w1 = wr[s1 * 9 + s2 * 3 + 1];
            float w2 = wr[s1 * 9 + s2 * 3 + 2];
            #pragma unroll
            for (int d = 0; d < 16; d++) {
                float a = w1 * col[d];
                if (d > 0)  a += w0 * col[d - 1];
                if (d < 15) a += w2 * col[d + 1];
                acc[d] += a;
            }
        }
    }
    int fh = (ori & 1) ? 15 - h : h;
    int fw = (ori & 2) ? 15 - w : w;
    #pragma unroll
    for (int d = 0; d < 16; d++) {
        float sv = acc[d] / (1.f + expf(-acc[d]));
        int fd = (ori & 4) ? 15 - d : d;
        size_t oi = ((size_t)b * LL + (fh * 16 + fw) * 16 + fd) * CC + c;
        split_store(sv, g_ahi, g_alo, oi);
    }
}

// ---------------- FUSED scan + gate: phases A+B+C+D, 128 blocks x 256 thr ----------------
__global__ __launch_bounds__(256)
void k_scanF(int layer, const float* __restrict__ dtw_, const float* __restrict__ dtb_,
             const float* __restrict__ Dv, int ori,
             const float* __restrict__ og, const float* __restrict__ ob) {
    extern __shared__ float sm[];
    float* rvS  = sm;                    // [CLN*256] rv (fast) or sp (generic)
    float* dxS  = sm + CLN * 256;        // [CLN*256] dtx, then y
    float* xvS  = sm + 2 * CLN * 256;    // [CLN*256] xv
    float* Bsm  = sm + 3 * CLN * 256;    // [CLN*16]
    float* Csm  = Bsm + CLN * 16;        // [CLN*16]
    float* dtsm = Csm + CLN * 16;        // [CLN*16]

    int tid = threadIdx.x;
    int c = tid;
    int ch = blockIdx.x, b = blockIdx.z;
    int fast = g_fastA[layer];

    for (int i = tid; i < CLN * 48; i += 256) {
        int t = i / 48, j = i % 48;
        float v = g_dbl[((size_t)b * LL + ch * CLN + t) * 48 + j];
        if (j < 16) dtsm[t * 16 + j] = v;
        else if (j < 32) Bsm[t * 16 + (j - 16)] = v;
        else Csm[t * 16 + (j - 32)] = v;
    }
    __syncthreads();

    float dw[DSZ];
    #pragma unroll
    for (int j = 0; j < DSZ; j++) dw[j] = dtw_[c * DSZ + j];
    float db = dtb_[c];

    // ---- phase A ----
    float h[DSZ], P[DSZ];
    #pragma unroll
    for (int n = 0; n < DSZ; n++) { h[n] = 0.f; P[n] = 1.f; }
    size_t base = ((size_t)b * LL + ch * CLN) * CC + c;
    if (fast) {
        #pragma unroll 4
        for (int t = 0; t < CLN; t++) {
            size_t gi = base + (size_t)t * CC;
            float xv = __bfloat162float(g_ahi[gi]) + __bfloat162float(g_alo[gi]);
            float traw = db;
            #pragma unroll
            for (int j = 0; j < DSZ; j++) traw += dw[j] * dtsm[t * 16 + j];
            float sp = fmaxf(traw, 0.f) + log1pf(expf(-fabsf(traw)));
            float rv = expf(-sp);
            float dtx = sp * xv;
            rvS[t * 256 + tid] = rv;
            dxS[t * 256 + tid] = dtx;
            xvS[t * 256 + tid] = xv;
            float rp[16];
            rpow16(rv, rp);
            #pragma unroll
            for (int n = 0; n < DSZ; n++) {
                h[n] = rp[n] * h[n] + dtx * Bsm[t * 16 + n];
                P[n] *= rp[n];
            }
        }
    } else {
        #pragma unroll 2
        for (int t = 0; t < CLN; t++) {
            size_t gi = base + (size_t)t * CC;
            float xv = __bfloat162float(g_ahi[gi]) + __bfloat162float(g_alo[gi]);
            float traw = db;
            #pragma unroll
            for (int j = 0; j < DSZ; j++) traw += dw[j] * dtsm[t * 16 + j];
            float sp = fmaxf(traw, 0.f) + log1pf(expf(-fabsf(traw)));
            float dtx = sp * xv;
            rvS[t * 256 + tid] = sp;
            dxS[t * 256 + tid] = dtx;
            xvS[t * 256 + tid] = xv;
            #pragma unroll
            for (int n = 0; n < DSZ; n++) {
                float dA = __expf(sp * g_A[((layer * 256) + c) * DSZ + n]);
                h[n] = dA * h[n] + dtx * Bsm[t * 16 + n];
                P[n] *= dA;
            }
        }
    }
    size_t off = (((size_t)(b * CC + c)) * NCH + ch) * DSZ;
    #pragma unroll
    for (int n = 0; n < DSZ; n++) { g_hend[off + n] = h[n]; g_P[off + n] = P[n]; }

    gridbar(0);

    // ---- phase B: sequential chunk combine ----
    {
        int rank = (blockIdx.z * NCH + blockIdx.x) * 256 + tid;
        if (rank < BB * CC * DSZ) {
            int n = rank & 15, bc = rank >> 4;
            float H = 0.f;
            size_t bb2 = (size_t)bc * NCH * DSZ + n;
            for (int k0 = 0; k0 < NCH; k0 += 8) {
                float Pv[8], Ev[8];
                #pragma unroll
                for (int q = 0; q < 8; q++) {
                    size_t o = bb2 + (size_t)(k0 + q) * DSZ;
                    Pv[q] = g_P[o];
                    Ev[q] = g_hend[o];
                }
                #pragma unroll
                for (int q = 0; q < 8; q++) {
                    g_hst[bb2 + (size_t)(k0 + q) * DSZ] = H;
                    H = Pv[q] * H + Ev[q];
                }
            }
        }
    }

    gridbar(1);

    // ---- phase C: replay, y -> smem (dxS slab) ----
    #pragma unroll
    for (int n = 0; n < DSZ; n++) h[n] = g_hst[off + n];
    float Dc = Dv[c];
    if (fast) {
        #pragma unroll 4
        for (int t = 0; t < CLN; t++) {
            float rv  = rvS[t * 256 + tid];
            float dtx = dxS[t * 256 + tid];
            float xv  = xvS[t * 256 + tid];
            float rp[16];
            rpow16(rv, rp);
            float y = 0.f;
            #pragma unroll
            for (int n = 0; n < DSZ; n++) {
                h[n] = rp[n] * h[n] + dtx * Bsm[t * 16 + n];
                y += h[n] * Csm[t * 16 + n];
            }
            dxS[t * 256 + tid] = y + Dc * xv;
        }
    } else {
        #pragma unroll 2
        for (int t = 0; t < CLN; t++) {
            float sp  = rvS[t * 256 + tid];
            float dtx = dxS[t * 256 + tid];
            float xv  = xvS[t * 256 + tid];
            float y = 0.f;
            #pragma unroll
            for (int n = 0; n < DSZ; n++) {
                float dA = __expf(sp * g_A[((layer * 256) + c) * DSZ + n]);
                h[n] = dA * h[n] + dtx * Bsm[t * 16 + n];
                y += h[n] * Csm[t * 16 + n];
            }
            dxS[t * 256 + tid] = y + Dc * xv;
        }
    }
    __syncthreads();

    // ---- phase D: LN + SiLU gate from smem, write splits at p = flip(q) ----
    {
        int warp = tid >> 5, lane = tid & 31;
        #pragma unroll
        for (int rr = 0; rr < 8; rr++) {
            int t = warp * 8 + rr;
            int q = ch * CLN + t;
            int hh = q >> 8, ww = (q >> 4) & 15, dd = q & 15;
            if (ori & 1) hh = 15 - hh;
            if (ori & 2) ww = 15 - ww;
            if (ori & 4) dd = 15 - dd;
            int p = (b << 12) | (hh << 8) | (ww << 4) | dd;
            const float4* yr = (const float4*)(dxS + t * 256);
            float4 v0 = yr[lane * 2], v1 = yr[lane * 2 + 1];
            float s  = v0.x + v0.y + v0.z + v0.w + v1.x + v1.y + v1.z + v1.w;
            float s2 = v0.x*v0.x + v0.y*v0.y + v0.z*v0.z + v0.w*v0.w
                     + v1.x*v1.x + v1.y*v1.y + v1.z*v1.z + v1.w*v1.w;
            warpRed2(s, s2);
            float m  = s * (1.f / CC);
            float rs = rsqrtf(s2 * (1.f / CC) - m * m + 1e-5f);
            const float4* zr = (const float4*)(g_xz + (size_t)p * 512 + 256);
            float4 z0 = zr[lane * 2], z1 = zr[lane * 2 + 1];
            float4 gg0 = ((const float4*)og)[lane * 2], gg1 = ((const float4*)og)[lane * 2 + 1];
            float4 bb0 = ((const float4*)ob)[lane * 2], bb1 = ((const float4*)ob)[lane * 2 + 1];
            float vv[8] = {v0.x, v0.y, v0.z, v0.w, v1.x, v1.y, v1.z, v1.w};
            float zz[8] = {z0.x, z0.y, z0.z, z0.w, z1.x, z1.y, z1.z, z1.w};
            float ga[8] = {gg0.x, gg0.y, gg0.z, gg0.w, gg1.x, gg1.y, gg1.z, gg1.w};
            float ba[8] = {bb0.x, bb0.y, bb0.z, bb0.w, bb1.x, bb1.y, bb1.z, bb1.w};
            float o[8];
            #pragma unroll
            for (int k = 0; k < 8; k++) {
                float sz = zz[k] / (1.f + expf(-zz[k]));
                o[k] = ((vv[k] - m) * rs * ga[k] + ba[k]) * sz;
            }
            split8_store(o, g_ahi, g_alo, (size_t)p * CC, lane);
        }
    }
}

// ---------------- post-LN stats ----------------
__global__ __launch_bounds__(256)
void k_stats() {
    int warp = threadIdx.x >> 5, lane = threadIdx.x & 31;
    int p = blockIdx.x * 8 + warp;
    const float4* row = (const float4*)(g_t + (size_t)p * CC);
    float4 v0 = row[lane * 2], v1 = row[lane * 2 + 1];
    float s  = v0.x + v0.y + v0.z + v0.w + v1.x + v1.y + v1.z + v1.w;
    float s2 = v0.x*v0.x + v0.y*v0.y + v0.z*v0.z + v0.w*v0.w
             + v1.x*v1.x + v1.y*v1.y + v1.z*v1.z + v1.w*v1.w;
    warpRed2(s, s2);
    if (lane == 0) {
        float m = s * (1.f / CC);
        g_rowm[p] = m;
        g_rowrs[p] = rsqrtf(s2 * (1.f / CC) - m * m + 1e-5f);
    }
}

// ---------------- final transpose + post-LN apply ----------------
__global__ void k_final_tr(float* __restrict__ out,
                           const float* __restrict__ pg, const float* __restrict__ pb) {
    __shared__ float tile[32][33];
    int b = blockIdx.z >> 4, d = blockIdx.z & 15;
    int hw0 = blockIdx.x * 32, c0 = blockIdx.y * 32;
    int tx = threadIdx.x, ty = threadIdx.y;
    int p = b * LL + (hw0 + ty) * 16 + d;
    int c = c0 + tx;
    float v = g_t[(size_t)p * CC + c];
    tile[ty][tx] = (v - g_rowm[p]) * g_rowrs[p] * pg[c] + pb[c];
    __syncthreads();
    out[((size_t)(b * CC + c0 + ty) * 16 + d) * 256 + hw0 + tx] = tile[tx][ty];
}

// ---------------- host ----------------
extern "C" void kernel_launch(void* const* d_in, const int* in_sizes, int n_in,
                              void* d_out, int out_size) {
    const float* x       = (const float*)d_in[0];
    const float* in_w    = (const float*)d_in[1];
    const float* conv_w  = (const float*)d_in[2];
    const float* conv_b  = (const float*)d_in[3];
    const float* xproj_w = (const float*)d_in[4];
    const float* dt_w    = (const float*)d_in[5];
    const float* dt_b    = (const float*)d_in[6];
    const float* A_log   = (const float*)d_in[7];
    const float* D_skip  = (const float*)d_in[8];
    const float* on_g    = (const float*)d_in[9];
    const float* on_b    = (const float*)d_in[10];
    const float* out_w   = (const float*)d_in[11];
    const float* ln1_g   = (const float*)d_in[12];
    const float* ln1_b   = (const float*)d_in[13];
    const float* post_g  = (const float*)d_in[14];
    const float* post_b  = (const float*)d_in[15];
    float* out = (float*)d_out;

    void *p_t, *p_xz, *p_dbl, *p_ahi, *p_alo, *p_whi, *p_wlo;
    cudaGetSymbolAddress(&p_t,   g_t);
    cudaGetSymbolAddress(&p_xz,  g_xz);
    cudaGetSymbolAddress(&p_dbl, g_dbl);
    cudaGetSymbolAddress(&p_ahi, g_ahi);
    cudaGetSymbolAddress(&p_alo, g_alo);
    cudaGetSymbolAddress(&p_whi, g_whi);
    cudaGetSymbolAddress(&p_wlo, g_wlo);
    const uint32_t* whi = (const uint32_t*)p_whi;
    const uint32_t* wlo = (const uint32_t*)p_wlo;

    const int SM128_2 = 2 * (2 * 128 * 80 + 2 * 128 * 80);    // 81920 B
    const int SM64_3  = 3 * (2 * 128 * 80 + 2 * 64 * 80);     // 92160 B
    const int SMEMF   = (3 * CLN * 256 + 3 * CLN * 16) * 4;   // 208896 B
    static int attr_done = 0;
    if (!attr_done) {
        cudaFuncSetAttribute((const void*)k_mgemm<128, 2>,
                             cudaFuncAttributeMaxDynamicSharedMemorySize, SM128_2);
        cudaFuncSetAttribute((const void*)k_mgemm<64, 3>,
                             cudaFuncAttributeMaxDynamicSharedMemorySize, SM64_3);
        cudaFuncSetAttribute((const void*)k_scanF,
                             cudaFuncAttributeMaxDynamicSharedMemorySize, SMEMF);
        attr_done = 1;
    }

    k_wsplit_all<<<(WTOT + 255) / 256, 256>>>(in_w, xproj_w, out_w);
    k_cwprep<<<108, 256>>>(conv_w);
    k_prepA_all<<<4, 256>>>(A_log);
    k_init_tr<<<dim3(8, 8, 32), dim3(32, 32)>>>(x);

    for (int i = 0; i < 4; i++) {
        int ori = i;  // i % 8
        k_ln1<<<1024, 256>>>(ln1_g + i * 256, ln1_b + i * 256);
        // in-proj: (8192 x 512), NT=128, 2-stage, 256 blocks (0.86 waves @ 2/SM)
        k_mgemm<128, 2><<<dim3(4, 64), 256, SM128_2>>>(
            (const uint32_t*)p_ahi, (const uint32_t*)p_alo,
            whi + WOFF_IN(i) / 2, wlo + WOFF_IN(i) / 2,
            (float*)p_xz, 512, 512, 0);
        k_conv<<<BB * 256, 256>>>(i, conv_b + i * 256, ori);
        // xproj: (8192 x 48), NT=64, 3-stage single-sync
        k_mgemm<64, 3><<<dim3(1, 64), 256, SM64_3>>>(
            (const uint32_t*)p_ahi, (const uint32_t*)p_alo,
            whi + WOFF_XP(i) / 2, wlo + WOFF_XP(i) / 2,
            (float*)p_dbl, 48, 48, 0);
        // fused scan (A+B+C) + gate (D, smem-resident)
        k_scanF<<<dim3(NCH, 1, BB), 256, SMEMF>>>(i, dt_w + (size_t)i * 4096,
                                                  dt_b + i * 256, D_skip + i * 256,
                                                  ori, on_g + i * 256, on_b + i * 256);
        // out-proj + residual, NT=64, 3-stage single-sync
        k_mgemm<64, 3><<<dim3(4, 64), 256, SM64_3>>>(
            (const uint32_t*)p_ahi, (const uint32_t*)p_alo,
            whi + WOFF_OUT(i) / 2, wlo + WOFF_OUT(i) / 2,
            (float*)p_t, 256, 256, 1);
    }

    k_stats<<<1024, 256>>>();
    k_final_tr<<<dim3(8, 8, 32), dim3(32, 32)>>>(out, post_g, post_b);
}

// round 16
// speedup vs baseline: 1.1183x; 1.0435x over previous
#include <cuda_runtime.h>
#include <cuda_bf16.h>
#include <math.h>
#include <stdint.h>

#define BB   2
#define CC   256
#define LL   4096
#define DSZ  16
#define NCH  64
#define CLN  64          // LL / NCH
#define NPOS (BB*LL)     // 8192
#define NBLK 128         // fused-scan grid size (1 block/SM, co-resident)

// weight-split buffer layout (bf16 elements)
#define WOFF_IN(i)   ((i) * 131072)
#define WOFF_XP(i)   (524288 + (i) * 16384)
#define WOFF_OUT(i)  (589824 + (i) * 65536)
#define WTOT 851968

// ---------------- scratch ----------------
__device__ float g_t[NPOS*CC];
__device__ float g_xz[NPOS*2*CC];
__device__ float g_dbl[NPOS*48];
__device__ float g_rowm[NPOS];
__device__ float g_rowrs[NPOS];
__device__ float g_A[4*CC*DSZ];
__device__ int   g_fastA[4];
__device__ float g_cw[4*27*CC];
__device__ float g_P[BB*CC*NCH*DSZ];
__device__ float g_hend[BB*CC*NCH*DSZ];
__device__ float g_hst[BB*CC*NCH*DSZ];
__device__ unsigned g_bar[2];
__device__ __nv_bfloat16 g_ahi[NPOS*CC];
__device__ __nv_bfloat16 g_alo[NPOS*CC];
__device__ __nv_bfloat16 g_whi[WTOT];
__device__ __nv_bfloat16 g_wlo[WTOT];

// ---------------- helpers ----------------
__device__ __forceinline__ uint32_t smem_u32(const void* p) {
    uint32_t a;
    asm("{ .reg .u64 t; cvta.to.shared.u64 t, %1; cvt.u32.u64 %0, t; }" : "=r"(a) : "l"(p));
    return a;
}
__device__ __forceinline__ void warpRed2(float& s, float& s2) {
    #pragma unroll
    for (int o = 16; o; o >>= 1) {
        s  += __shfl_xor_sync(0xffffffffu, s,  o);
        s2 += __shfl_xor_sync(0xffffffffu, s2, o);
    }
}
__device__ __forceinline__ uint32_t packbf2(float a, float b) {
    __nv_bfloat162 t = __floats2bfloat162_rn(a, b);
    return *(uint32_t*)&t;
}
__device__ __forceinline__ void split8_store(const float o[8],
                                             __nv_bfloat16* hiB, __nv_bfloat16* loB,
                                             size_t rowoff, int lane) {
    float hf[8], lf[8];
    #pragma unroll
    for (int k = 0; k < 8; k++) {
        __nv_bfloat16 h = __float2bfloat16(o[k]);
        hf[k] = __bfloat162float(h);
        lf[k] = o[k] - hf[k];
    }
    uint4 uh, ul;
    uh.x = packbf2(hf[0], hf[1]); uh.y = packbf2(hf[2], hf[3]);
    uh.z = packbf2(hf[4], hf[5]); uh.w = packbf2(hf[6], hf[7]);
    ul.x = packbf2(lf[0], lf[1]); ul.y = packbf2(lf[2], lf[3]);
    ul.z = packbf2(lf[4], lf[5]); ul.w = packbf2(lf[6], lf[7]);
    ((uint4*)(hiB + rowoff))[lane] = uh;
    ((uint4*)(loB + rowoff))[lane] = ul;
}
__device__ __forceinline__ void split_store(float v, __nv_bfloat16* hi, __nv_bfloat16* lo, size_t i) {
    __nv_bfloat16 h = __float2bfloat16(v);
    hi[i] = h;
    lo[i] = __float2bfloat16(v - __bfloat162float(h));
}
__device__ __forceinline__ void mma16816(float c[4], const uint32_t a[4],
                                         uint32_t b0, uint32_t b1) {
    asm volatile(
        "mma.sync.aligned.m16n8k16.row.col.f32.bf16.bf16.f32 "
        "{%0,%1,%2,%3}, {%4,%5,%6,%7}, {%8,%9}, {%0,%1,%2,%3};"
        : "+f"(c[0]), "+f"(c[1]), "+f"(c[2]), "+f"(c[3])
        : "r"(a[0]), "r"(a[1]), "r"(a[2]), "r"(a[3]), "r"(b0), "r"(b1));
}
__device__ __forceinline__ void ldsm4(uint32_t r[4], uint32_t addr) {
    asm volatile("ldmatrix.sync.aligned.m8n8.x4.shared.b16 {%0,%1,%2,%3}, [%4];"
        : "=r"(r[0]), "=r"(r[1]), "=r"(r[2]), "=r"(r[3]) : "r"(addr));
}
__device__ __forceinline__ void cpa16(uint32_t saddr, const void* g) {
    asm volatile("cp.async.cg.shared.global [%0], [%1], 16;" :: "r"(saddr), "l"(g));
}
#define CPA_COMMIT() asm volatile("cp.async.commit_group;" ::: "memory")
#define CPA_WAIT(N)  asm volatile("cp.async.wait_group %0;" :: "n"(N) : "memory")

// r^1..r^16 via log-depth tree
__device__ __forceinline__ void rpow16(float rv, float rp[16]) {
    float r2 = rv * rv, r4 = r2 * r2, r8 = r4 * r4;
    rp[0] = rv;        rp[1] = r2;        rp[2] = r2 * rv;   rp[3] = r4;
    rp[4] = r4 * rv;   rp[5] = r4 * r2;   rp[6] = r4 * rp[2]; rp[7] = r8;
    rp[8] = r8 * rv;   rp[9] = r8 * r2;   rp[10] = r8 * rp[2]; rp[11] = r8 * r4;
    rp[12] = r8 * rp[4]; rp[13] = r8 * rp[5]; rp[14] = r8 * rp[6]; rp[15] = r8 * r8;
}

// fast softplus + exp(-softplus): 3 MUFU total
__device__ __forceinline__ void softplus_fast(float traw, float& sp, float& rv) {
    float e = __expf(-fabsf(traw));
    sp = fmaxf(traw, 0.f) + __logf(1.f + e);
    rv = __expf(-sp);
}
__device__ __forceinline__ float silu_fast(float x) {
    return __fdividef(x, 1.f + __expf(-x));
}

// monotonic-ticket grid barrier
__device__ __forceinline__ void gridbar(int slot) {
    __syncthreads();
    if (threadIdx.x == 0) {
        __threadfence();
        unsigned ticket = atomicAdd(&g_bar[slot], 1u) + 1u;
        unsigned target = ((ticket - 1u) / NBLK + 1u) * NBLK;
        while ((int)(*(volatile unsigned*)&g_bar[slot] - target) < 0) { }
        __threadfence();
    }
    __syncthreads();
}

// ---------------- all-layer weight split ----------------
__global__ void k_wsplit_all(const float* __restrict__ inw,
                             const float* __restrict__ xpw,
                             const float* __restrict__ ow) {
    int idx = blockIdx.x * 256 + threadIdx.x;
    if (idx >= WTOT) return;
    float v;
    if (idx < 524288) {
        v = inw[idx];
    } else if (idx < 589824) {
        int rel = idx - 524288;
        int layer = rel >> 14, w = rel & 16383;
        int row = w >> 8, col = w & 255;
        v = (row < 48) ? xpw[layer * 12288 + row * 256 + col] : 0.f;
    } else {
        v = ow[idx - 589824];
    }
    split_store(v, g_whi, g_wlo, idx);
}

// ---------------- conv weight transpose ----------------
__global__ void k_cwprep(const float* __restrict__ cw) {
    int idx = blockIdx.x * 256 + threadIdx.x;
    if (idx >= 4 * 27 * 256) return;
    int layer = idx / 6912, rem = idx % 6912;
    int j = rem >> 8, c = rem & 255;
    g_cw[idx] = cw[layer * 6912 + c * 27 + j];
}

// ---------------- all-layer A prep ----------------
__global__ void k_prepA_all(const float* __restrict__ alog) {
    int layer = blockIdx.x, c = threadIdx.x;
    __shared__ int ok;
    if (c == 0) ok = 1;
    __syncthreads();
    bool good = true;
    #pragma unroll
    for (int n = 0; n < DSZ; n++) {
        float a = -expf(alog[(layer * 256 + c) * DSZ + n]);
        g_A[(layer * 256 + c) * DSZ + n] = a;
        if (fabsf(a + (float)(n + 1)) > 1e-3f) good = false;
    }
    if (!good) atomicAnd(&ok, 0);
    __syncthreads();
    if (c == 0) g_fastA[layer] = ok;
}

// ---------------- initial transpose ----------------
__global__ void k_init_tr(const float* __restrict__ x) {
    __shared__ float tile[32][33];
    int b = blockIdx.z >> 4, d = blockIdx.z & 15;
    int hw0 = blockIdx.x * 32, c0 = blockIdx.y * 32;
    int tx = threadIdx.x, ty = threadIdx.y;
    tile[ty][tx] = x[((size_t)(b*CC + c0 + ty) * 16 + d) * 256 + hw0 + tx];
    __syncthreads();
    g_t[((size_t)b*LL + (size_t)(hw0 + ty) * 16 + d) * CC + c0 + tx] = tile[tx][ty];
}

// ---------------- LN1 (warp per row) + bf16 split ----------------
__global__ __launch_bounds__(256)
void k_ln1(const float* __restrict__ g, const float* __restrict__ bvec) {
    int warp = threadIdx.x >> 5, lane = threadIdx.x & 31;
    int p = blockIdx.x * 8 + warp;
    const float4* row = (const float4*)(g_t + (size_t)p * CC);
    float4 v0 = row[lane * 2], v1 = row[lane * 2 + 1];
    float s  = v0.x + v0.y + v0.z + v0.w + v1.x + v1.y + v1.z + v1.w;
    float s2 = v0.x*v0.x + v0.y*v0.y + v0.z*v0.z + v0.w*v0.w
             + v1.x*v1.x + v1.y*v1.y + v1.z*v1.z + v1.w*v1.w;
    warpRed2(s, s2);
    float m  = s * (1.f / CC);
    float rs = rsqrtf(s2 * (1.f / CC) - m * m + 1e-5f);
    float4 gg0 = ((const float4*)g)[lane * 2],    gg1 = ((const float4*)g)[lane * 2 + 1];
    float4 bb0 = ((const float4*)bvec)[lane * 2], bb1 = ((const float4*)bvec)[lane * 2 + 1];
    float o[8];
    o[0] = (v0.x - m) * rs * gg0.x + bb0.x;  o[1] = (v0.y - m) * rs * gg0.y + bb0.y;
    o[2] = (v0.z - m) * rs * gg0.z + bb0.z;  o[3] = (v0.w - m) * rs * gg0.w + bb0.w;
    o[4] = (v1.x - m) * rs * gg1.x + bb1.x;  o[5] = (v1.y - m) * rs * gg1.y + bb1.y;
    o[6] = (v1.z - m) * rs * gg1.z + bb1.z;  o[7] = (v1.w - m) * rs * gg1.w + bb1.w;
    split8_store(o, g_ahi, g_alo, (size_t)p * CC, lane);
}

// ---------------- pipelined ldmatrix bf16x3 GEMM, STG-stage (R15, kept) ----------------
template<int NT, int STG>
__global__ __launch_bounds__(256, 2)
void k_mgemm(const uint32_t* __restrict__ Ahi, const uint32_t* __restrict__ Alo,
             const uint32_t* __restrict__ Bhi, const uint32_t* __restrict__ Blo,
             float* __restrict__ C, int ldc, int Nact, int mode) {
    constexpr int RB = 80;
    constexpr int AL_OFF = 128 * RB;
    constexpr int BH_OFF = 2 * 128 * RB;
    constexpr int BL_OFF = BH_OFF + NT * RB;
    constexpr int STAGE  = BH_OFF + 2 * NT * RB;
    constexpr int NTILES = NT / 16;
    constexpr int NPAIR  = NTILES / 2;

    extern __shared__ __align__(16) char smem[];
    uint32_t sbase = smem_u32(smem);
    int tid = threadIdx.x, wid = tid >> 5, lane = tid & 31;
    int g2 = lane >> 2, t4 = lane & 3;
    int row0 = blockIdx.y * 128, col0 = blockIdx.x * NT;
    int m0 = (wid >> 1) * 32, n0 = (wid & 1) * (NT / 2);
    uint32_t lmo = (uint32_t)(((lane & 7) + ((lane >> 3) & 1) * 8) * RB + (lane >> 4) * 16);

    float acc[2][NTILES][4];
    #pragma unroll
    for (int mt = 0; mt < 2; mt++)
        #pragma unroll
        for (int nt = 0; nt < NTILES; nt++)
            #pragma unroll
            for (int j = 0; j < 4; j++) acc[mt][nt][j] = 0.f;

    int lr = tid >> 2, lc4 = (tid & 3) * 4;

    auto load_chunk = [&](int kc, int stg) {
        uint32_t sb = sbase + stg * STAGE;
        int kw = kc * 16;
        #pragma unroll
        for (int i = 0; i < 2; i++) {
            int r = lr + i * 64;
            size_t gi = (size_t)(row0 + r) * 128 + kw + lc4;
            uint32_t so = (uint32_t)(r * RB + lc4 * 4);
            cpa16(sb + so,          Ahi + gi);
            cpa16(sb + AL_OFF + so, Alo + gi);
        }
        #pragma unroll
        for (int i = 0; i < NT / 64; i++) {
            int r = lr + i * 64;
            size_t gi = (size_t)(col0 + r) * 128 + kw + lc4;
            uint32_t so = (uint32_t)(r * RB + lc4 * 4);
            cpa16(sb + BH_OFF + so, Bhi + gi);
            cpa16(sb + BL_OFF + so, Blo + gi);
        }
    };

    auto compute_chunk = [&](int stg) {
        uint32_t sb = sbase + stg * STAGE;
        uint32_t aH = sb + m0 * RB + lmo;
        uint32_t aL = aH + AL_OFF;
        uint32_t bH = sb + BH_OFF + n0 * RB + lmo;
        uint32_t bL = bH + NT * RB;
        #pragma unroll
        for (int step = 0; step < 2; step++) {
            uint32_t ko = step * 32;
            uint32_t ah[2][4], al[2][4];
            #pragma unroll
            for (int mt = 0; mt < 2; mt++) {
                ldsm4(ah[mt], aH + mt * 16 * RB + ko);
                ldsm4(al[mt], aL + mt * 16 * RB + ko);
            }
            #pragma unroll
            for (int p = 0; p < NPAIR; p++) {
                uint32_t bh[4], bl[4];
                ldsm4(bh, bH + p * 16 * RB + ko);
                ldsm4(bl, bL + p * 16 * RB + ko);
                #pragma unroll
                for (int sub = 0; sub < 2; sub++) {
                    uint32_t b0h = bh[sub], b1h = bh[2 + sub];
                    uint32_t b0l = bl[sub], b1l = bl[2 + sub];
                    #pragma unroll
                    for (int mt = 0; mt < 2; mt++) {
                        mma16816(acc[mt][2 * p + sub], ah[mt], b0h, b1h);
                        mma16816(acc[mt][2 * p + sub], ah[mt], b0l, b1l);
                        mma16816(acc[mt][2 * p + sub], al[mt], b0h, b1h);
                    }
                }
            }
        }
    };

    load_chunk(0, 0); CPA_COMMIT();
    load_chunk(1, 1); CPA_COMMIT();

    if (STG == 3) {
        #pragma unroll 1
        for (int kc = 0; kc < 8; kc++) {
            if (kc < 7) { CPA_WAIT(1); } else { CPA_WAIT(0); }
            __syncthreads();
            if (kc + 2 < 8) { load_chunk(kc + 2, (kc + 2) % 3); CPA_COMMIT(); }
            compute_chunk(kc % 3);
        }
    } else {
        #pragma unroll 1
        for (int kc = 0; kc < 8; kc++) {
            if (kc < 7) { CPA_WAIT(1); } else { CPA_WAIT(0); }
            __syncthreads();
            compute_chunk(kc & 1);
            __syncthreads();
            if (kc + 2 < 8) { load_chunk(kc + 2, kc & 1); CPA_COMMIT(); }
        }
    }

    #pragma unroll
    for (int mt = 0; mt < 2; mt++) {
        int rA = row0 + m0 + mt * 16 + g2;
        int rB = rA + 8;
        #pragma unroll
        for (int nt = 0; nt < NTILES; nt++) {
            int cA = col0 + n0 + nt * 8 + 2 * t4;
            #pragma unroll
            for (int j = 0; j < 2; j++) {
                int c = cA + j;
                if (c < Nact) {
                    float v0 = acc[mt][nt][j];
                    float v1 = acc[mt][nt][2 + j];
                    if (mode == 1) {
                        v0 += C[(size_t)rA * ldc + c];
                        v1 += C[(size_t)rB * ldc + c];
                    }
                    C[(size_t)rA * ldc + c] = v0;
                    C[(size_t)rB * ldc + c] = v1;
                }
            }
        }
    }
}

// ---------------- depthwise 3x3x3 conv + SiLU + flip ----------------
__global__ __launch_bounds__(256)
void k_conv(int layer, const float* __restrict__ convb, int ori) {
    int bidx = blockIdx.x;
    int b = bidx >> 8, h = (bidx >> 4) & 15, w = bidx & 15;
    int c = threadIdx.x;
    const float* wt = g_cw + layer * 6912;
    float wr[27];
    #pragma unroll
    for (int j = 0; j < 27; j++) wr[j] = wt[j * 256 + c];
    float bias = convb[c];
    float acc[16];
    #pragma unroll
    for (int d = 0; d < 16; d++) acc[d] = bias;

    #pragma unroll
    for (int s1 = 0; s1 < 3; s1++) {
        int hh = h + s1 - 1; if (hh < 0 || hh > 15) continue;
        #pragma unroll
        for (int s2 = 0; s2 < 3; s2++) {
            int ww = w + s2 - 1; if (ww < 0 || ww > 15) continue;
            size_t cb = ((size_t)(b * LL + (hh * 16 + ww) * 16)) * 512 + c;
            float col[16];
            #pragma unroll
            for (int dd = 0; dd < 16; dd++) col[dd] = g_xz[cb + (size_t)dd * 512];
            float w0 = wr[s1 * 9 + s2 * 3 + 0];
            float w1 = wr[s1 * 9 + s2 * 3 + 1];
            float w2 = wr[s1 * 9 + s2 * 3 + 2];
            #pragma unroll
            for (int d = 0; d < 16; d++) {
                float a = w1 * col[d];
                if (d > 0)  a += w0 * col[d - 1];
                if (d < 15) a += w2 * col[d + 1];
                acc[d] += a;
            }
        }
    }
    int fh = (ori & 1) ? 15 - h : h;
    int fw = (ori & 2) ? 15 - w : w;
    #pragma unroll
    for (int d = 0; d < 16; d++) {
        float sv = silu_fast(acc[d]);
        int fd = (ori & 4) ? 15 - d : d;
        size_t oi = ((size_t)b * LL + (fh * 16 + fw) * 16 + fd) * CC + c;
        split_store(sv, g_ahi, g_alo, oi);
    }
}

// ---------------- FUSED scan + gate: phases A+B+C+D, 128 blocks x 256 thr ----------------
__global__ __launch_bounds__(256)
void k_scanF(int layer, const float* __restrict__ dtw_, const float* __restrict__ dtb_,
             const float* __restrict__ Dv, int ori,
             const float* __restrict__ og, const float* __restrict__ ob) {
    extern __shared__ float sm[];
    float* rvS  = sm;                    // [CLN*256] rv (fast) or sp (generic)
    float* dxS  = sm + CLN * 256;        // [CLN*256] dtx, then y
    float* xvS  = sm + 2 * CLN * 256;    // [CLN*256] xv
    float* Bsm  = sm + 3 * CLN * 256;    // [CLN*16]
    float* Csm  = Bsm + CLN * 16;        // [CLN*16]
    float* dtsm = Csm + CLN * 16;        // [CLN*16]

    int tid = threadIdx.x;
    int c = tid;
    int ch = blockIdx.x, b = blockIdx.z;
    int fast = g_fastA[layer];

    for (int i = tid; i < CLN * 48; i += 256) {
        int t = i / 48, j = i % 48;
        float v = g_dbl[((size_t)b * LL + ch * CLN + t) * 48 + j];
        if (j < 16) dtsm[t * 16 + j] = v;
        else if (j < 32) Bsm[t * 16 + (j - 16)] = v;
        else Csm[t * 16 + (j - 32)] = v;
    }
    __syncthreads();

    float dw[DSZ];
    #pragma unroll
    for (int j = 0; j < DSZ; j++) dw[j] = dtw_[c * DSZ + j];
    float db = dtb_[c];

    // ---- phase A ----
    float h[DSZ], P[DSZ];
    #pragma unroll
    for (int n = 0; n < DSZ; n++) { h[n] = 0.f; P[n] = 1.f; }
    size_t base = ((size_t)b * LL + ch * CLN) * CC + c;
    if (fast) {
        #pragma unroll 4
        for (int t = 0; t < CLN; t++) {
            size_t gi = base + (size_t)t * CC;
            float xv = __bfloat162float(g_ahi[gi]) + __bfloat162float(g_alo[gi]);
            float traw = db;
            #pragma unroll
            for (int j = 0; j < DSZ; j++) traw += dw[j] * dtsm[t * 16 + j];
            float sp, rv;
            softplus_fast(traw, sp, rv);
            float dtx = sp * xv;
            rvS[t * 256 + tid] = rv;
            dxS[t * 256 + tid] = dtx;
            xvS[t * 256 + tid] = xv;
            float rp[16];
            rpow16(rv, rp);
            #pragma unroll
            for (int n = 0; n < DSZ; n++) {
                h[n] = rp[n] * h[n] + dtx * Bsm[t * 16 + n];
                P[n] *= rp[n];
            }
        }
    } else {
        #pragma unroll 2
        for (int t = 0; t < CLN; t++) {
            size_t gi = base + (size_t)t * CC;
            float xv = __bfloat162float(g_ahi[gi]) + __bfloat162float(g_alo[gi]);
            float traw = db;
            #pragma unroll
            for (int j = 0; j < DSZ; j++) traw += dw[j] * dtsm[t * 16 + j];
            float sp, rv_unused;
            softplus_fast(traw, sp, rv_unused);
            float dtx = sp * xv;
            rvS[t * 256 + tid] = sp;
            dxS[t * 256 + tid] = dtx;
            xvS[t * 256 + tid] = xv;
            #pragma unroll
            for (int n = 0; n < DSZ; n++) {
                float dA = __expf(sp * g_A[((layer * 256) + c) * DSZ + n]);
                h[n] = dA * h[n] + dtx * Bsm[t * 16 + n];
                P[n] *= dA;
            }
        }
    }
    size_t off = (((size_t)(b * CC + c)) * NCH + ch) * DSZ;
    #pragma unroll
    for (int n = 0; n < DSZ; n++) { g_hend[off + n] = h[n]; g_P[off + n] = P[n]; }

    gridbar(0);

    // ---- phase B: sequential chunk combine ----
    {
        int rank = (blockIdx.z * NCH + blockIdx.x) * 256 + tid;
        if (rank < BB * CC * DSZ) {
            int n = rank & 15, bc = rank >> 4;
            float H = 0.f;
            size_t bb2 = (size_t)bc * NCH * DSZ + n;
            for (int k0 = 0; k0 < NCH; k0 += 8) {
                float Pv[8], Ev[8];
                #pragma unroll
                for (int q = 0; q < 8; q++) {
                    size_t o = bb2 + (size_t)(k0 + q) * DSZ;
                    Pv[q] = g_P[o];
                    Ev[q] = g_hend[o];
                }
                #pragma unroll
                for (int q = 0; q < 8; q++) {
                    g_hst[bb2 + (size_t)(k0 + q) * DSZ] = H;
                    H = Pv[q] * H + Ev[q];
                }
            }
        }
    }

    gridbar(1);

    // ---- phase C: replay, y -> smem (dxS slab) ----
    #pragma unroll
    for (int n = 0; n < DSZ; n++) h[n] = g_hst[off + n];
    float Dc = Dv[c];
    if (fast) {
        #pragma unroll 4
        for (int t = 0; t < CLN; t++) {
            float rv  = rvS[t * 256 + tid];
            float dtx = dxS[t * 256 + tid];
            float xv  = xvS[t * 256 + tid];
            float rp[16];
            rpow16(rv, rp);
            float y = 0.f;
            #pragma unroll
            for (int n = 0; n < DSZ; n++) {
                h[n] = rp[n] * h[n] + dtx * Bsm[t * 16 + n];
                y += h[n] * Csm[t * 16 + n];
            }
            dxS[t * 256 + tid] = y + Dc * xv;
        }
    } else {
        #pragma unroll 2
        for (int t = 0; t < CLN; t++) {
            float sp  = rvS[t * 256 + tid];
            float dtx = dxS[t * 256 + tid];
            float xv  = xvS[t * 256 + tid];
            float y = 0.f;
            #pragma unroll
            for (int n = 0; n < DSZ; n++) {
                float dA = __expf(sp * g_A[((layer * 256) + c) * DSZ + n]);
                h[n] = dA * h[n] + dtx * Bsm[t * 16 + n];
                y += h[n] * Csm[t * 16 + n];
            }
            dxS[t * 256 + tid] = y + Dc * xv;
        }
    }
    __syncthreads();

    // ---- phase D: LN + SiLU gate from smem, write splits at p = flip(q) ----
    {
        int warp = tid >> 5, lane = tid & 31;
        #pragma unroll
        for (int rr = 0; rr < 8; rr++) {
            int t = warp * 8 + rr;
            int q = ch * CLN + t;
            int hh = q >> 8, ww = (q >> 4) & 15, dd = q & 15;
            if (ori & 1) hh = 15 - hh;
            if (ori & 2) ww = 15 - ww;
            if (ori & 4) dd = 15 - dd;
            int p = (b << 12) | (hh << 8) | (ww << 4) | dd;
            const float4* yr = (const float4*)(dxS + t * 256);
            float4 v0 = yr[lane * 2], v1 = yr[lane * 2 + 1];
            float s  = v0.x + v0.y + v0.z + v0.w + v1.x + v1.y + v1.z + v1.w;
            float s2 = v0.x*v0.x + v0.y*v0.y + v0.z*v0.z + v0.w*v0.w
                     + v1.x*v1.x + v1.y*v1.y + v1.z*v1.z + v1.w*v1.w;
            warpRed2(s, s2);
            float m  = s * (1.f / CC);
            float rs = rsqrtf(s2 * (1.f / CC) - m * m + 1e-5f);
            const float4* zr = (const float4*)(g_xz + (size_t)p * 512 + 256);
            float4 z0 = zr[lane * 2], z1 = zr[lane * 2 + 1];
            float4 gg0 = ((const float4*)og)[lane * 2], gg1 = ((const float4*)og)[lane * 2 + 1];
            float4 bb0 = ((const float4*)ob)[lane * 2], bb1 = ((const float4*)ob)[lane * 2 + 1];
            float vv[8] = {v0.x, v0.y, v0.z, v0.w, v1.x, v1.y, v1.z, v1.w};
            float zz[8] = {z0.x, z0.y, z0.z, z0.w, z1.x, z1.y, z1.z, z1.w};
            float ga[8] = {gg0.x, gg0.y, gg0.z, gg0.w, gg1.x, gg1.y, gg1.z, gg1.w};
            float ba[8] = {bb0.x, bb0.y, bb0.z, bb0.w, bb1.x, bb1.y, bb1.z, bb1.w};
            float o[8];
            #pragma unroll
            for (int k = 0; k < 8; k++) {
                float sz = silu_fast(zz[k]);
                o[k] = ((vv[k] - m) * rs * ga[k] + ba[k]) * sz;
            }
            split8_store(o, g_ahi, g_alo, (size_t)p * CC, lane);
        }
    }
}

// ---------------- post-LN stats ----------------
__global__ __launch_bounds__(256)
void k_stats() {
    int warp = threadIdx.x >> 5, lane = threadIdx.x & 31;
    int p = blockIdx.x * 8 + warp;
    const float4* row = (const float4*)(g_t + (size_t)p * CC);
    float4 v0 = row[lane * 2], v1 = row[lane * 2 + 1];
    float s  = v0.x + v0.y + v0.z + v0.w + v1.x + v1.y + v1.z + v1.w;
    float s2 = v0.x*v0.x + v0.y*v0.y + v0.z*v0.z + v0.w*v0.w
             + v1.x*v1.x + v1.y*v1.y + v1.z*v1.z + v1.w*v1.w;
    warpRed2(s, s2);
    if (lane == 0) {
        float m = s * (1.f / CC);
        g_rowm[p] = m;
        g_rowrs[p] = rsqrtf(s2 * (1.f / CC) - m * m + 1e-5f);
    }
}

// ---------------- final transpose + post-LN apply ----------------
__global__ void k_final_tr(float* __restrict__ out,
                           const float* __restrict__ pg, const float* __restrict__ pb) {
    __shared__ float tile[32][33];
    int b = blockIdx.z >> 4, d = blockIdx.z & 15;
    int hw0 = blockIdx.x * 32, c0 = blockIdx.y * 32;
    int tx = threadIdx.x, ty = threadIdx.y;
    int p = b * LL + (hw0 + ty) * 16 + d;
    int c = c0 + tx;
    float v = g_t[(size_t)p * CC + c];
    tile[ty][tx] = (v - g_rowm[p]) * g_rowrs[p] * pg[c] + pb[c];
    __syncthreads();
    out[((size_t)(b * CC + c0 + ty) * 16 + d) * 256 + hw0 + tx] = tile[tx][ty];
}

// ---------------- host ----------------
extern "C" void kernel_launch(void* const* d_in, const int* in_sizes, int n_in,
                              void* d_out, int out_size) {
    const float* x       = (const float*)d_in[0];
    const float* in_w    = (const float*)d_in[1];
    const float* conv_w  = (const float*)d_in[2];
    const float* conv_b  = (const float*)d_in[3];
    const float* xproj_w = (const float*)d_in[4];
    const float* dt_w    = (const float*)d_in[5];
    const float* dt_b    = (const float*)d_in[6];
    const float* A_log   = (const float*)d_in[7];
    const float* D_skip  = (const float*)d_in[8];
    const float* on_g    = (const float*)d_in[9];
    const float* on_b    = (const float*)d_in[10];
    const float* out_w   = (const float*)d_in[11];
    const float* ln1_g   = (const float*)d_in[12];
    const float* ln1_b   = (const float*)d_in[13];
    const float* post_g  = (const float*)d_in[14];
    const float* post_b  = (const float*)d_in[15];
    float* out = (float*)d_out;

    void *p_t, *p_xz, *p_dbl, *p_ahi, *p_alo, *p_whi, *p_wlo;
    cudaGetSymbolAddress(&p_t,   g_t);
    cudaGetSymbolAddress(&p_xz,  g_xz);
    cudaGetSymbolAddress(&p_dbl, g_dbl);
    cudaGetSymbolAddress(&p_ahi, g_ahi);
    cudaGetSymbolAddress(&p_alo, g_alo);
    cudaGetSymbolAddress(&p_whi, g_whi);
    cudaGetSymbolAddress(&p_wlo, g_wlo);
    const uint32_t* whi = (const uint32_t*)p_whi;
    const uint32_t* wlo = (const uint32_t*)p_wlo;

    const int SM128_2 = 2 * (2 * 128 * 80 + 2 * 128 * 80);    // 81920 B
    const int SM64_3  = 3 * (2 * 128 * 80 + 2 * 64 * 80);     // 92160 B
    const int SMEMF   = (3 * CLN * 256 + 3 * CLN * 16) * 4;   // 208896 B
    static int attr_done = 0;
    if (!attr_done) {
        cudaFuncSetAttribute((const void*)k_mgemm<128, 2>,
                             cudaFuncAttributeMaxDynamicSharedMemorySize, SM128_2);
        cudaFuncSetAttribute((const void*)k_mgemm<64, 3>,
                             cudaFuncAttributeMaxDynamicSharedMemorySize, SM64_3);
        cudaFuncSetAttribute((const void*)k_scanF,
                             cudaFuncAttributeMaxDynamicSharedMemorySize, SMEMF);
        attr_done = 1;
    }

    k_wsplit_all<<<(WTOT + 255) / 256, 256>>>(in_w, xproj_w, out_w);
    k_cwprep<<<108, 256>>>(conv_w);
    k_prepA_all<<<4, 256>>>(A_log);
    k_init_tr<<<dim3(8, 8, 32), dim3(32, 32)>>>(x);

    for (int i = 0; i < 4; i++) {
        int ori = i;  // i % 8
        k_ln1<<<1024, 256>>>(ln1_g + i * 256, ln1_b + i * 256);
        // in-proj: (8192 x 512), NT=128, 2-stage
        k_mgemm<128, 2><<<dim3(4, 64), 256, SM128_2>>>(
            (const uint32_t*)p_ahi, (const uint32_t*)p_alo,
            whi + WOFF_IN(i) / 2, wlo + WOFF_IN(i) / 2,
            (float*)p_xz, 512, 512, 0);
        k_conv<<<BB * 256, 256>>>(i, conv_b + i * 256, ori);
        // xproj: (8192 x 48), NT=64, 3-stage single-sync
        k_mgemm<64, 3><<<dim3(1, 64), 256, SM64_3>>>(
            (const uint32_t*)p_ahi, (const uint32_t*)p_alo,
            whi + WOFF_XP(i) / 2, wlo + WOFF_XP(i) / 2,
            (float*)p_dbl, 48, 48, 0);
        // fused scan (A+B+C) + gate (D, smem-resident)
        k_scanF<<<dim3(NCH, 1, BB), 256, SMEMF>>>(i, dt_w + (size_t)i * 4096,
                                                  dt_b + i * 256, D_skip + i * 256,
                                                  ori, on_g + i * 256, on_b + i * 256);
        // out-proj + residual, NT=64, 3-stage single-sync
        k_mgemm<64, 3><<<dim3(4, 64), 256, SM64_3>>>(
            (const uint32_t*)p_ahi, (const uint32_t*)p_alo,
            whi + WOFF_OUT(i) / 2, wlo + WOFF_OUT(i) / 2,
            (float*)p_t, 256, 256, 1);
    }

    k_stats<<<1024, 256>>>();
    k_final_tr<<<dim3(8, 8, 32), dim3(32, 32)>>>(out, post_g, post_b);
}